// round 6
// baseline (speedup 1.0000x reference)
#include <cuda_runtime.h>
#include <cuda_bf16.h>

#define NU 339
#define NI 5825
#define NN 6164          // NU + NI
#define BB 32768
#define SS 20
#define DD 128
#define FF 8
#define GM (BB * SS)     // 655360 rows of G

// Scratch (device globals: allocation-free per harness rules)
__device__ float g_adjx[NN * DD];                  // 3.2 MB
__device__ float g_G[(size_t)GM * DD];             // 335 MB
__device__ float g_t2[(size_t)BB * 2 * 256];       // 67 MB

// ---------------------------------------------------------------------------
// Kernel A: adj_x = l2norm(user_infos@Wu + bu) ++ l2norm(item_infos@Wi + bi)
// ---------------------------------------------------------------------------
__global__ __launch_bounds__(DD) void adjx_kernel(
    const float* __restrict__ user_infos, const float* __restrict__ item_infos,
    const float* __restrict__ Wu, const float* __restrict__ bu,
    const float* __restrict__ Wi, const float* __restrict__ bi)
{
    int r = blockIdx.x;
    int d = threadIdx.x;
    const float* feat;
    const float* W;
    const float* bv;
    if (r < NU) { feat = user_infos + r * FF;        W = Wu; bv = bu; }
    else        { feat = item_infos + (r - NU) * FF; W = Wi; bv = bi; }

    float acc = bv[d];
#pragma unroll
    for (int f = 0; f < FF; f++) acc = fmaf(feat[f], W[f * DD + d], acc);

    __shared__ float red[4];
    float sq = acc * acc;
#pragma unroll
    for (int o = 16; o > 0; o >>= 1) sq += __shfl_xor_sync(0xffffffffu, sq, o);
    if ((threadIdx.x & 31) == 0) red[threadIdx.x >> 5] = sq;
    __syncthreads();
    float tot = red[0] + red[1] + red[2] + red[3];
    float nrm = fmaxf(sqrtf(tot), 1e-12f);
    g_adjx[r * DD + d] = acc / nrm;
}

// ---------------------------------------------------------------------------
// Kernel B: G build. warp-per-element, register accumulators.
// Block = 256 thr = 8 warps = 8 elements. grid = BB/8.
// ---------------------------------------------------------------------------
__global__ __launch_bounds__(256) void g_build_kernel(
    const int* __restrict__ sample_ids, const float* __restrict__ adj)
{
    __shared__ int   s_sid[8 * SS];
    __shared__ float s_adj[8][SS][SS];

    const int tid = threadIdx.x;
    const int w = tid >> 5, lane = tid & 31;

    if (tid < 8 * SS) s_sid[tid] = sample_ids[blockIdx.x * 8 * SS + tid];
    __syncthreads();

    for (int id = tid; id < 8 * SS * SS; id += 256) {
        int e = id / 400, rem = id % 400, i = rem / SS, j = rem % SS;
        s_adj[e][i][j] =
            __ldg(&adj[(long)s_sid[e * SS + i] * NN + s_sid[e * SS + j]]);
    }
    __syncthreads();

    float4 acc[SS];
#pragma unroll
    for (int i = 0; i < SS; i++) acc[i] = make_float4(0.f, 0.f, 0.f, 0.f);

#pragma unroll 4
    for (int j = 0; j < SS; j++) {
        float4 sx = __ldg((const float4*)&g_adjx[(long)s_sid[w * SS + j] * DD
                                                 + lane * 4]);
#pragma unroll
        for (int i = 0; i < SS; i++) {
            float a = s_adj[w][i][j];
            acc[i].x = fmaf(a, sx.x, acc[i].x);
            acc[i].y = fmaf(a, sx.y, acc[i].y);
            acc[i].z = fmaf(a, sx.z, acc[i].z);
            acc[i].w = fmaf(a, sx.w, acc[i].w);
        }
    }

    const long rbase = (long)(blockIdx.x * 8 + w) * SS;
#pragma unroll
    for (int i = 0; i < SS; i++)
        *(float4*)&g_G[(rbase + i) * DD + lane * 4] = acc[i];
}

// ---------------------------------------------------------------------------
// Kernel C: GEMM H1 = relu(G@W1 + b1) with fused root-contraction epilogue.
// M-tile 160 (8 elements), N-tile 128 (grid.y=2), K=128 in chunks of 32.
// 320 threads, 8x8 microtile. Epilogue: t2[e][r] += adj[root_r] . relu(h1).
// s_t2 aliases Bs (Bs dead after main loop).
// ---------------------------------------------------------------------------
__global__ __launch_bounds__(320, 2) void gemm_kernel(
    const int*   __restrict__ sample_ids,
    const int*   __restrict__ roots,
    const float* __restrict__ adj,
    const float* __restrict__ W1, const float* __restrict__ b1)
{
    __shared__ float As[160][36];        // 23040 B (row stride 144B, 16B-aligned)
    __shared__ float Bs[32][132];        // 16896 B (row stride 528B, 16B-aligned)
    __shared__ float s_ar[8][2][SS];     //  1280 B
    __shared__ int   s_sid[160];         //   640 B   (total 41856 B)

    const int tid = threadIdx.x;
    const int tx = tid & 15, ty = tid >> 4;         // tx: 16 col-groups, ty: 20 row-groups
    const long m0 = (long)blockIdx.x * 160;
    const int  b0 = blockIdx.x * 8;
    const int  n0 = blockIdx.y * 128;

    if (tid < 160) s_sid[tid] = sample_ids[m0 + tid];
    __syncthreads();

    // gather the 2 root-rows of each element's sub-adj
    {
        int e = tid / 40, r = (tid / 20) & 1, j = tid % 20;
        int rt = __ldg(&roots[(b0 + e) * 2 + r]);
        s_ar[e][r][j] =
            __ldg(&adj[(long)s_sid[e * SS + rt] * NN + s_sid[e * SS + j]]);
    }

    float acc[8][8];
    {
        float4 bv0 = *(const float4*)&b1[n0 + tx * 8];
        float4 bv1 = *(const float4*)&b1[n0 + tx * 8 + 4];
#pragma unroll
        for (int i = 0; i < 8; i++) {
            acc[i][0] = bv0.x; acc[i][1] = bv0.y; acc[i][2] = bv0.z; acc[i][3] = bv0.w;
            acc[i][4] = bv1.x; acc[i][5] = bv1.y; acc[i][6] = bv1.z; acc[i][7] = bv1.w;
        }
    }

    for (int k0 = 0; k0 < DD; k0 += 32) {
        // A tile: 160 x 32 (1280 float4, coalesced; 16B-aligned rows)
#pragma unroll
        for (int p = 0; p < 4; p++) {
            int f4 = p * 320 + tid;
            int r = f4 >> 3, q = f4 & 7;
            *(float4*)&As[r][q * 4] =
                *(const float4*)&g_G[(m0 + r) * DD + k0 + q * 4];
        }
        // B tile: 32 x 128 (1024 float4)
        for (int id = tid; id < 1024; id += 320) {
            int k = id >> 5, cq = id & 31;
            *(float4*)&Bs[k][cq * 4] =
                *(const float4*)&W1[(long)(k0 + k) * 256 + n0 + cq * 4];
        }
        __syncthreads();

#pragma unroll 4
        for (int kk = 0; kk < 32; kk++) {
            float a[8], bb[8];
#pragma unroll
            for (int i = 0; i < 8; i++) a[i] = As[ty * 8 + i][kk];
            *(float4*)&bb[0] = *(const float4*)&Bs[kk][tx * 8];
            *(float4*)&bb[4] = *(const float4*)&Bs[kk][tx * 8 + 4];
#pragma unroll
            for (int i = 0; i < 8; i++)
#pragma unroll
                for (int j = 0; j < 8; j++)
                    acc[i][j] = fmaf(a[i], bb[j], acc[i][j]);
        }
        __syncthreads();
    }

    // ---- epilogue: relu + contract with root rows; s_t2 aliases Bs ----
    float* s_t2 = &Bs[0][0];             // 2048 floats needed (8*2*128) <= 4224
    for (int id = tid; id < 2048; id += 320) s_t2[id] = 0.f;
    __syncthreads();

#pragma unroll
    for (int i = 0; i < 8; i++) {
        int row = ty * 8 + i;
        int e = row / SS, il = row % SS;
        float w0 = s_ar[e][0][il];
        float w1 = s_ar[e][1][il];
#pragma unroll
        for (int j = 0; j < 8; j++) {
            float v = fmaxf(acc[i][j], 0.f);
            atomicAdd(&s_t2[(e * 2 + 0) * 128 + tx * 8 + j], w0 * v);
            atomicAdd(&s_t2[(e * 2 + 1) * 128 + tx * 8 + j], w1 * v);
        }
    }
    __syncthreads();

    for (int id = tid; id < 2048; id += 320) {
        int e = id >> 8, r = (id >> 7) & 1, c = id & 127;
        g_t2[(long)(b0 + e) * 512 + r * 256 + n0 + c] = s_t2[id];
    }
}

// ---------------------------------------------------------------------------
// Kernel D: tail, 8 elements per block, 256 threads.
// ---------------------------------------------------------------------------
__global__ __launch_bounds__(256) void tail_kernel(
    const int*   __restrict__ user_idx,
    const int*   __restrict__ item_idx,
    const float* __restrict__ uid_emb,
    const float* __restrict__ sid_emb,
    const float* __restrict__ W2, const float* __restrict__ b2,
    const float* __restrict__ mW0, const float* __restrict__ mb0,
    const float* __restrict__ mW1, const float* __restrict__ mb1,
    const float* __restrict__ mW2, const float* __restrict__ mb2,
    float* __restrict__ out)
{
    __shared__ float bufA[4096];
    __shared__ float wB[8192];

    const int tid = threadIdx.x;
    const int tx = tid & 31, ty = tid >> 5;   // ty: 0..7
    const int b0 = blockIdx.x * 8;

    // load t2 for 8 elements (contiguous 4096 floats)
    {
        const float4* src = (const float4*)(g_t2 + (long)b0 * 512);
        for (int id = tid; id < 1024; id += 256) ((float4*)bufA)[id] = src[id];
    }
    __syncthreads();

    // ---- ft = relu(t2 @ W2 + b2): rows er = {ty, ty+8}, cols d = tx*4+c ----
    float f[2][4] = {{0.f,0.f,0.f,0.f},{0.f,0.f,0.f,0.f}};
    for (int c0 = 0; c0 < 256; c0 += 64) {
        for (int id = tid; id < 2048; id += 256) {
            int k = id >> 5, dq = id & 31;
            *(float4*)&wB[k * 128 + dq * 4] =
                *(const float4*)&W2[(long)(c0 + k) * 128 + dq * 4];
        }
        __syncthreads();
#pragma unroll 8
        for (int kk = 0; kk < 64; kk++) {
            float4 w4 = *(const float4*)&wB[kk * 128 + tx * 4];
            float t0 = bufA[ty * 256 + c0 + kk];
            float t1 = bufA[(ty + 8) * 256 + c0 + kk];
            f[0][0] = fmaf(t0, w4.x, f[0][0]); f[0][1] = fmaf(t0, w4.y, f[0][1]);
            f[0][2] = fmaf(t0, w4.z, f[0][2]); f[0][3] = fmaf(t0, w4.w, f[0][3]);
            f[1][0] = fmaf(t1, w4.x, f[1][0]); f[1][1] = fmaf(t1, w4.y, f[1][1]);
            f[1][2] = fmaf(t1, w4.z, f[1][2]); f[1][3] = fmaf(t1, w4.w, f[1][3]);
        }
        __syncthreads();
    }

    // merge with id_vec into x at bufA[0:2048]; x[e][r*128+d]
    {
        float4 bv = *(const float4*)&b2[tx * 4];
        float bias[4] = {bv.x, bv.y, bv.z, bv.w};
#pragma unroll
        for (int s = 0; s < 2; s++) {
            int er = ty + s * 8;
            int e = er >> 1, r = er & 1;
            const float* emb = (r == 0)
                ? &uid_emb[(long)__ldg(&user_idx[b0 + e]) * DD]
                : &sid_emb[(long)__ldg(&item_idx[b0 + e]) * DD];
            float4 idv = __ldg((const float4*)&emb[tx * 4]);
            float xv[4];
            xv[0] = 0.6f * idv.x + 0.4f * fmaxf(f[s][0] + bias[0], 0.f);
            xv[1] = 0.6f * idv.y + 0.4f * fmaxf(f[s][1] + bias[1], 0.f);
            xv[2] = 0.6f * idv.z + 0.4f * fmaxf(f[s][2] + bias[2], 0.f);
            xv[3] = 0.6f * idv.w + 0.4f * fmaxf(f[s][3] + bias[3], 0.f);
            f[s][0] = xv[0]; f[s][1] = xv[1]; f[s][2] = xv[2]; f[s][3] = xv[3];
        }
    }
    __syncthreads();   // all t2 reads done; safe to overwrite bufA
#pragma unroll
    for (int s = 0; s < 2; s++) {
        int er = ty + s * 8;
        int e = er >> 1, r = er & 1;
        *(float4*)&bufA[e * 256 + r * 128 + tx * 4] = *(float4*)&f[s][0];
    }
    __syncthreads();

    // ---- MLP0: y1 = relu(x @ mW0 + mb0): out (e=ty, o=tx*4+c) ----
    float g0[4] = {0.f, 0.f, 0.f, 0.f};
    for (int c0 = 0; c0 < 256; c0 += 64) {
        for (int id = tid; id < 2048; id += 256) {
            int k = id >> 5, dq = id & 31;
            *(float4*)&wB[k * 128 + dq * 4] =
                *(const float4*)&mW0[(long)(c0 + k) * 128 + dq * 4];
        }
        __syncthreads();
#pragma unroll 8
        for (int kk = 0; kk < 64; kk++) {
            float4 w4 = *(const float4*)&wB[kk * 128 + tx * 4];
            float xv = bufA[ty * 256 + c0 + kk];
            g0[0] = fmaf(xv, w4.x, g0[0]); g0[1] = fmaf(xv, w4.y, g0[1]);
            g0[2] = fmaf(xv, w4.z, g0[2]); g0[3] = fmaf(xv, w4.w, g0[3]);
        }
        __syncthreads();
    }
    {
        float4 bv = __ldg((const float4*)&mb0[tx * 4]);
        float4 y;
        y.x = fmaxf(g0[0] + bv.x, 0.f); y.y = fmaxf(g0[1] + bv.y, 0.f);
        y.z = fmaxf(g0[2] + bv.z, 0.f); y.w = fmaxf(g0[3] + bv.w, 0.f);
        *(float4*)&bufA[2048 + ty * 128 + tx * 4] = y;   // y1[e=ty][128]
    }
    // load mW1 whole (8192 floats) into wB
    for (int id = tid; id < 2048; id += 256)
        ((float4*)wB)[id] = __ldg(&((const float4*)mW1)[id]);
    __syncthreads();

    // ---- MLP1: y2 = relu(y1 @ mW1 + mb1): out (e=ty, o=tx*2..+1) ----
    {
        int oo = tx * 2;
        float a0 = 0.f, a1 = 0.f;
#pragma unroll 4
        for (int k = 0; k < 128; k++) {
            float yv = bufA[2048 + ty * 128 + k];
            float2 w2 = *(const float2*)&wB[k * 64 + oo];
            a0 = fmaf(yv, w2.x, a0);
            a1 = fmaf(yv, w2.y, a1);
        }
        float2 bv = __ldg((const float2*)&mb1[oo]);
        bufA[3072 + ty * 64 + oo]     = fmaxf(a0 + bv.x, 0.f);
        bufA[3072 + ty * 64 + oo + 1] = fmaxf(a1 + bv.y, 0.f);
    }
    __syncthreads();

    // ---- MLP2: warp ty handles element ty ----
    {
        float p = bufA[3072 + ty * 64 + tx] * __ldg(&mW2[tx]) +
                  bufA[3072 + ty * 64 + 32 + tx] * __ldg(&mW2[32 + tx]);
#pragma unroll
        for (int o = 16; o > 0; o >>= 1) p += __shfl_xor_sync(0xffffffffu, p, o);
        if (tx == 0) out[b0 + ty] = fmaxf(p + __ldg(&mb2[0]), 0.f);
    }
}

// ---------------------------------------------------------------------------
extern "C" void kernel_launch(void* const* d_in, const int* in_sizes, int n_in,
                              void* d_out, int out_size)
{
    const int*   user_indexes = (const int*)  d_in[0];
    const int*   item_indexes = (const int*)  d_in[1];
    const int*   sample_ids   = (const int*)  d_in[2];
    const int*   roots        = (const int*)  d_in[3];
    const float* user_infos   = (const float*)d_in[4];
    const float* item_infos   = (const float*)d_in[5];
    const float* adj_matrix   = (const float*)d_in[6];
    const float* uid_emb      = (const float*)d_in[7];
    const float* sid_emb      = (const float*)d_in[8];
    const float* Wu           = (const float*)d_in[9];
    const float* bu           = (const float*)d_in[10];
    const float* Wi           = (const float*)d_in[11];
    const float* bi           = (const float*)d_in[12];
    const float* W1           = (const float*)d_in[13];
    const float* b1           = (const float*)d_in[14];
    const float* W2           = (const float*)d_in[15];
    const float* b2           = (const float*)d_in[16];
    const float* mW0          = (const float*)d_in[17];
    const float* mb0          = (const float*)d_in[18];
    const float* mW1          = (const float*)d_in[19];
    const float* mb1          = (const float*)d_in[20];
    const float* mW2          = (const float*)d_in[21];
    const float* mb2          = (const float*)d_in[22];
    float* out = (float*)d_out;

    adjx_kernel<<<NN, DD>>>(user_infos, item_infos, Wu, bu, Wi, bi);
    g_build_kernel<<<BB / 8, 256>>>(sample_ids, adj_matrix);
    gemm_kernel<<<dim3(GM / 160, 2), 320>>>(sample_ids, roots, adj_matrix, W1, b1);
    tail_kernel<<<BB / 8, 256>>>(user_indexes, item_indexes, uid_emb, sid_emb,
                                 W2, b2, mW0, mb0, mW1, mb1, mW2, mb2,
                                 out);
}

// round 7
// speedup vs baseline: 1.2418x; 1.2418x over previous
#include <cuda_runtime.h>
#include <cuda_bf16.h>

#define NU 339
#define NI 5825
#define NN 6164          // NU + NI
#define BB 32768
#define SS 20
#define DD 128
#define FF 8
#define GM (BB * SS)     // 655360 rows of G

// Scratch (device globals: allocation-free per harness rules)
__device__ float g_adjx[NN * DD];                  // 3.2 MB
__device__ float g_G[(size_t)GM * DD];             // 335 MB
__device__ float g_t2[(size_t)BB * 2 * 256];       // 67 MB

// ---------------------------------------------------------------------------
// Kernel A: adj_x = l2norm(user_infos@Wu + bu) ++ l2norm(item_infos@Wi + bi)
// ---------------------------------------------------------------------------
__global__ __launch_bounds__(DD) void adjx_kernel(
    const float* __restrict__ user_infos, const float* __restrict__ item_infos,
    const float* __restrict__ Wu, const float* __restrict__ bu,
    const float* __restrict__ Wi, const float* __restrict__ bi)
{
    int r = blockIdx.x;
    int d = threadIdx.x;
    const float* feat;
    const float* W;
    const float* bv;
    if (r < NU) { feat = user_infos + r * FF;        W = Wu; bv = bu; }
    else        { feat = item_infos + (r - NU) * FF; W = Wi; bv = bi; }

    float acc = bv[d];
#pragma unroll
    for (int f = 0; f < FF; f++) acc = fmaf(feat[f], W[f * DD + d], acc);

    __shared__ float red[4];
    float sq = acc * acc;
#pragma unroll
    for (int o = 16; o > 0; o >>= 1) sq += __shfl_xor_sync(0xffffffffu, sq, o);
    if ((threadIdx.x & 31) == 0) red[threadIdx.x >> 5] = sq;
    __syncthreads();
    float tot = red[0] + red[1] + red[2] + red[3];
    float nrm = fmaxf(sqrtf(tot), 1e-12f);
    g_adjx[r * DD + d] = acc / nrm;
}

// ---------------------------------------------------------------------------
// Kernel B: G build. warp-per-element, register accumulators.
// Block = 256 thr = 8 warps = 8 elements. grid = BB/8.
// ---------------------------------------------------------------------------
__global__ __launch_bounds__(256) void g_build_kernel(
    const int* __restrict__ sample_ids, const float* __restrict__ adj)
{
    __shared__ int   s_sid[8 * SS];
    __shared__ float s_adj[8][SS][SS];

    const int tid = threadIdx.x;
    const int w = tid >> 5, lane = tid & 31;

    if (tid < 8 * SS) s_sid[tid] = sample_ids[blockIdx.x * 8 * SS + tid];
    __syncthreads();

    for (int id = tid; id < 8 * SS * SS; id += 256) {
        int e = id / 400, rem = id % 400, i = rem / SS, j = rem % SS;
        s_adj[e][i][j] =
            __ldg(&adj[(long)s_sid[e * SS + i] * NN + s_sid[e * SS + j]]);
    }
    __syncthreads();

    float4 acc[SS];
#pragma unroll
    for (int i = 0; i < SS; i++) acc[i] = make_float4(0.f, 0.f, 0.f, 0.f);

#pragma unroll 4
    for (int j = 0; j < SS; j++) {
        float4 sx = __ldg((const float4*)&g_adjx[(long)s_sid[w * SS + j] * DD
                                                 + lane * 4]);
#pragma unroll
        for (int i = 0; i < SS; i++) {
            float a = s_adj[w][i][j];
            acc[i].x = fmaf(a, sx.x, acc[i].x);
            acc[i].y = fmaf(a, sx.y, acc[i].y);
            acc[i].z = fmaf(a, sx.z, acc[i].z);
            acc[i].w = fmaf(a, sx.w, acc[i].w);
        }
    }

    const long rbase = (long)(blockIdx.x * 8 + w) * SS;
#pragma unroll
    for (int i = 0; i < SS; i++)
        *(float4*)&g_G[(rbase + i) * DD + lane * 4] = acc[i];
}

// ---------------------------------------------------------------------------
// Kernel C: GEMM H1 = relu(G@W1 + b1) with fused root-contraction epilogue.
// M-tile 160 (8 elements), N-tile 128 (grid.y=2), K=128 in chunks of 32.
// 512 threads, 5x8 microtile (40 accs -> ~80 regs, NO spills, no occ clamp).
// tx = tid&15 (16 col-groups of 8), ty = tid>>4 (32 row-groups of 5).
// Epilogue: t2[e][r] += adj[root_r] . relu(h1); s_t2 aliases Bs.
// ---------------------------------------------------------------------------
__global__ __launch_bounds__(512) void gemm_kernel(
    const int*   __restrict__ sample_ids,
    const int*   __restrict__ roots,
    const float* __restrict__ adj,
    const float* __restrict__ W1, const float* __restrict__ b1)
{
    __shared__ float As[160][36];        // 23040 B (stride 144B = 9*16, aligned)
    __shared__ float Bs[32][132];        // 16896 B (stride 528B = 33*16, aligned)
    __shared__ float s_ar[8][2][SS];     //  1280 B
    __shared__ int   s_sid[160];         //   640 B   (total 41856 B)

    const int tid = threadIdx.x;
    const int tx = tid & 15, ty = tid >> 4;      // ty: 0..31
    const long m0 = (long)blockIdx.x * 160;
    const int  b0 = blockIdx.x * 8;
    const int  n0 = blockIdx.y * 128;

    if (tid < 160) s_sid[tid] = sample_ids[m0 + tid];
    __syncthreads();

    // gather the 2 root-rows of each element's sub-adj
    if (tid < 320) {
        int e = tid / 40, r = (tid / 20) & 1, j = tid % 20;
        int rt = __ldg(&roots[(b0 + e) * 2 + r]);
        s_ar[e][r][j] =
            __ldg(&adj[(long)s_sid[e * SS + rt] * NN + s_sid[e * SS + j]]);
    }

    float acc[5][8];
    {
        float4 bv0 = *(const float4*)&b1[n0 + tx * 8];
        float4 bv1 = *(const float4*)&b1[n0 + tx * 8 + 4];
#pragma unroll
        for (int i = 0; i < 5; i++) {
            acc[i][0] = bv0.x; acc[i][1] = bv0.y; acc[i][2] = bv0.z; acc[i][3] = bv0.w;
            acc[i][4] = bv1.x; acc[i][5] = bv1.y; acc[i][6] = bv1.z; acc[i][7] = bv1.w;
        }
    }

    for (int k0 = 0; k0 < DD; k0 += 32) {
        // A tile: 160 x 32 (1280 float4, coalesced)
        for (int f4 = tid; f4 < 1280; f4 += 512) {
            int r = f4 >> 3, q = f4 & 7;
            *(float4*)&As[r][q * 4] =
                *(const float4*)&g_G[(m0 + r) * DD + k0 + q * 4];
        }
        // B tile: 32 x 128 (1024 float4, coalesced)
        for (int id = tid; id < 1024; id += 512) {
            int k = id >> 5, cq = id & 31;
            *(float4*)&Bs[k][cq * 4] =
                *(const float4*)&W1[(long)(k0 + k) * 256 + n0 + cq * 4];
        }
        __syncthreads();

#pragma unroll 8
        for (int kk = 0; kk < 32; kk++) {
            float a[5], bb[8];
#pragma unroll
            for (int i = 0; i < 5; i++) a[i] = As[ty * 5 + i][kk];
            *(float4*)&bb[0] = *(const float4*)&Bs[kk][tx * 8];
            *(float4*)&bb[4] = *(const float4*)&Bs[kk][tx * 8 + 4];
#pragma unroll
            for (int i = 0; i < 5; i++)
#pragma unroll
                for (int j = 0; j < 8; j++)
                    acc[i][j] = fmaf(a[i], bb[j], acc[i][j]);
        }
        __syncthreads();
    }

    // ---- epilogue: relu + contract with root rows; s_t2 aliases Bs ----
    float* s_t2 = &Bs[0][0];             // needs 2048 floats <= 4224 available
    for (int id = tid; id < 2048; id += 512) s_t2[id] = 0.f;
    __syncthreads();

    {
        const int e = ty >> 2;           // 4 ty-groups (of 5 rows) per element
        const int il0 = (ty & 3) * 5;    // local row base within element
#pragma unroll
        for (int r = 0; r < 2; r++) {
            float part[8] = {0.f, 0.f, 0.f, 0.f, 0.f, 0.f, 0.f, 0.f};
#pragma unroll
            for (int i = 0; i < 5; i++) {
                float w = s_ar[e][r][il0 + i];
#pragma unroll
                for (int j = 0; j < 8; j++)
                    part[j] = fmaf(w, fmaxf(acc[i][j], 0.f), part[j]);
            }
#pragma unroll
            for (int j = 0; j < 8; j++)
                atomicAdd(&s_t2[(e * 2 + r) * 128 + tx * 8 + j], part[j]);
        }
    }
    __syncthreads();

    for (int id = tid; id < 2048; id += 512) {
        int e = id >> 8, r = (id >> 7) & 1, c = id & 127;
        g_t2[(long)(b0 + e) * 512 + r * 256 + n0 + c] = s_t2[id];
    }
}

// ---------------------------------------------------------------------------
// Kernel D: tail, 8 elements per block, 256 threads.
// ---------------------------------------------------------------------------
__global__ __launch_bounds__(256) void tail_kernel(
    const int*   __restrict__ user_idx,
    const int*   __restrict__ item_idx,
    const float* __restrict__ uid_emb,
    const float* __restrict__ sid_emb,
    const float* __restrict__ W2, const float* __restrict__ b2,
    const float* __restrict__ mW0, const float* __restrict__ mb0,
    const float* __restrict__ mW1, const float* __restrict__ mb1,
    const float* __restrict__ mW2, const float* __restrict__ mb2,
    float* __restrict__ out)
{
    __shared__ float bufA[4096];
    __shared__ float wB[8192];

    const int tid = threadIdx.x;
    const int tx = tid & 31, ty = tid >> 5;   // ty: 0..7
    const int b0 = blockIdx.x * 8;

    // load t2 for 8 elements (contiguous 4096 floats)
    {
        const float4* src = (const float4*)(g_t2 + (long)b0 * 512);
        for (int id = tid; id < 1024; id += 256) ((float4*)bufA)[id] = src[id];
    }
    __syncthreads();

    // ---- ft = relu(t2 @ W2 + b2): rows er = {ty, ty+8}, cols d = tx*4+c ----
    float f[2][4] = {{0.f,0.f,0.f,0.f},{0.f,0.f,0.f,0.f}};
    for (int c0 = 0; c0 < 256; c0 += 64) {
        for (int id = tid; id < 2048; id += 256) {
            int k = id >> 5, dq = id & 31;
            *(float4*)&wB[k * 128 + dq * 4] =
                *(const float4*)&W2[(long)(c0 + k) * 128 + dq * 4];
        }
        __syncthreads();
#pragma unroll 8
        for (int kk = 0; kk < 64; kk++) {
            float4 w4 = *(const float4*)&wB[kk * 128 + tx * 4];
            float t0 = bufA[ty * 256 + c0 + kk];
            float t1 = bufA[(ty + 8) * 256 + c0 + kk];
            f[0][0] = fmaf(t0, w4.x, f[0][0]); f[0][1] = fmaf(t0, w4.y, f[0][1]);
            f[0][2] = fmaf(t0, w4.z, f[0][2]); f[0][3] = fmaf(t0, w4.w, f[0][3]);
            f[1][0] = fmaf(t1, w4.x, f[1][0]); f[1][1] = fmaf(t1, w4.y, f[1][1]);
            f[1][2] = fmaf(t1, w4.z, f[1][2]); f[1][3] = fmaf(t1, w4.w, f[1][3]);
        }
        __syncthreads();
    }

    // merge with id_vec into x at bufA[0:2048]; x[e][r*128+d]
    {
        float4 bv = *(const float4*)&b2[tx * 4];
        float bias[4] = {bv.x, bv.y, bv.z, bv.w};
#pragma unroll
        for (int s = 0; s < 2; s++) {
            int er = ty + s * 8;
            int e = er >> 1, r = er & 1;
            const float* emb = (r == 0)
                ? &uid_emb[(long)__ldg(&user_idx[b0 + e]) * DD]
                : &sid_emb[(long)__ldg(&item_idx[b0 + e]) * DD];
            float4 idv = __ldg((const float4*)&emb[tx * 4]);
            float xv[4];
            xv[0] = 0.6f * idv.x + 0.4f * fmaxf(f[s][0] + bias[0], 0.f);
            xv[1] = 0.6f * idv.y + 0.4f * fmaxf(f[s][1] + bias[1], 0.f);
            xv[2] = 0.6f * idv.z + 0.4f * fmaxf(f[s][2] + bias[2], 0.f);
            xv[3] = 0.6f * idv.w + 0.4f * fmaxf(f[s][3] + bias[3], 0.f);
            f[s][0] = xv[0]; f[s][1] = xv[1]; f[s][2] = xv[2]; f[s][3] = xv[3];
        }
    }
    __syncthreads();   // all t2 reads done; safe to overwrite bufA
#pragma unroll
    for (int s = 0; s < 2; s++) {
        int er = ty + s * 8;
        int e = er >> 1, r = er & 1;
        *(float4*)&bufA[e * 256 + r * 128 + tx * 4] = *(float4*)&f[s][0];
    }
    __syncthreads();

    // ---- MLP0: y1 = relu(x @ mW0 + mb0): out (e=ty, o=tx*4+c) ----
    float g0[4] = {0.f, 0.f, 0.f, 0.f};
    for (int c0 = 0; c0 < 256; c0 += 64) {
        for (int id = tid; id < 2048; id += 256) {
            int k = id >> 5, dq = id & 31;
            *(float4*)&wB[k * 128 + dq * 4] =
                *(const float4*)&mW0[(long)(c0 + k) * 128 + dq * 4];
        }
        __syncthreads();
#pragma unroll 8
        for (int kk = 0; kk < 64; kk++) {
            float4 w4 = *(const float4*)&wB[kk * 128 + tx * 4];
            float xv = bufA[ty * 256 + c0 + kk];
            g0[0] = fmaf(xv, w4.x, g0[0]); g0[1] = fmaf(xv, w4.y, g0[1]);
            g0[2] = fmaf(xv, w4.z, g0[2]); g0[3] = fmaf(xv, w4.w, g0[3]);
        }
        __syncthreads();
    }
    {
        float4 bv = __ldg((const float4*)&mb0[tx * 4]);
        float4 y;
        y.x = fmaxf(g0[0] + bv.x, 0.f); y.y = fmaxf(g0[1] + bv.y, 0.f);
        y.z = fmaxf(g0[2] + bv.z, 0.f); y.w = fmaxf(g0[3] + bv.w, 0.f);
        *(float4*)&bufA[2048 + ty * 128 + tx * 4] = y;   // y1[e=ty][128]
    }
    // load mW1 whole (8192 floats) into wB
    for (int id = tid; id < 2048; id += 256)
        ((float4*)wB)[id] = __ldg(&((const float4*)mW1)[id]);
    __syncthreads();

    // ---- MLP1: y2 = relu(y1 @ mW1 + mb1): out (e=ty, o=tx*2..+1) ----
    {
        int oo = tx * 2;
        float a0 = 0.f, a1 = 0.f;
#pragma unroll 4
        for (int k = 0; k < 128; k++) {
            float yv = bufA[2048 + ty * 128 + k];
            float2 w2 = *(const float2*)&wB[k * 64 + oo];
            a0 = fmaf(yv, w2.x, a0);
            a1 = fmaf(yv, w2.y, a1);
        }
        float2 bv = __ldg((const float2*)&mb1[oo]);
        bufA[3072 + ty * 64 + oo]     = fmaxf(a0 + bv.x, 0.f);
        bufA[3072 + ty * 64 + oo + 1] = fmaxf(a1 + bv.y, 0.f);
    }
    __syncthreads();

    // ---- MLP2: warp ty handles element ty ----
    {
        float p = bufA[3072 + ty * 64 + tx] * __ldg(&mW2[tx]) +
                  bufA[3072 + ty * 64 + 32 + tx] * __ldg(&mW2[32 + tx]);
#pragma unroll
        for (int o = 16; o > 0; o >>= 1) p += __shfl_xor_sync(0xffffffffu, p, o);
        if (tx == 0) out[b0 + ty] = fmaxf(p + __ldg(&mb2[0]), 0.f);
    }
}

// ---------------------------------------------------------------------------
extern "C" void kernel_launch(void* const* d_in, const int* in_sizes, int n_in,
                              void* d_out, int out_size)
{
    const int*   user_indexes = (const int*)  d_in[0];
    const int*   item_indexes = (const int*)  d_in[1];
    const int*   sample_ids   = (const int*)  d_in[2];
    const int*   roots        = (const int*)  d_in[3];
    const float* user_infos   = (const float*)d_in[4];
    const float* item_infos   = (const float*)d_in[5];
    const float* adj_matrix   = (const float*)d_in[6];
    const float* uid_emb      = (const float*)d_in[7];
    const float* sid_emb      = (const float*)d_in[8];
    const float* Wu           = (const float*)d_in[9];
    const float* bu           = (const float*)d_in[10];
    const float* Wi           = (const float*)d_in[11];
    const float* bi           = (const float*)d_in[12];
    const float* W1           = (const float*)d_in[13];
    const float* b1           = (const float*)d_in[14];
    const float* W2           = (const float*)d_in[15];
    const float* b2           = (const float*)d_in[16];
    const float* mW0          = (const float*)d_in[17];
    const float* mb0          = (const float*)d_in[18];
    const float* mW1          = (const float*)d_in[19];
    const float* mb1          = (const float*)d_in[20];
    const float* mW2          = (const float*)d_in[21];
    const float* mb2          = (const float*)d_in[22];
    float* out = (float*)d_out;

    adjx_kernel<<<NN, DD>>>(user_infos, item_infos, Wu, bu, Wi, bi);
    g_build_kernel<<<BB / 8, 256>>>(sample_ids, adj_matrix);
    gemm_kernel<<<dim3(GM / 160, 2), 512>>>(sample_ids, roots, adj_matrix, W1, b1);
    tail_kernel<<<BB / 8, 256>>>(user_indexes, item_indexes, uid_emb, sid_emb,
                                 W2, b2, mW0, mb0, mW1, mb1, mW2, mb2,
                                 out);
}

// round 9
// speedup vs baseline: 4.1357x; 3.3303x over previous
#include <cuda_runtime.h>
#include <cuda_bf16.h>

#define NU 339
#define NI 5825
#define NN 6164          // NU + NI
#define BB 32768
#define SS 20
#define DD 128
#define FF 8

// Scratch (device globals: allocation-free per harness rules)
__device__ float g_adjx[NN * DD];                  // 3.2 MB
__device__ float g_AX1[NN * 2 * DD];               // 6.3 MB (L2-resident)
__device__ float g_t2[(size_t)BB * 2 * 256];       // 67 MB

// ---------------------------------------------------------------------------
// Kernel A: adj_x = l2norm(user_infos@Wu + bu) ++ l2norm(item_infos@Wi + bi)
// ---------------------------------------------------------------------------
__global__ __launch_bounds__(DD) void adjx_kernel(
    const float* __restrict__ user_infos, const float* __restrict__ item_infos,
    const float* __restrict__ Wu, const float* __restrict__ bu,
    const float* __restrict__ Wi, const float* __restrict__ bi)
{
    int r = blockIdx.x;
    int d = threadIdx.x;
    const float* feat;
    const float* W;
    const float* bv;
    if (r < NU) { feat = user_infos + r * FF;        W = Wu; bv = bu; }
    else        { feat = item_infos + (r - NU) * FF; W = Wi; bv = bi; }

    float acc = bv[d];
#pragma unroll
    for (int f = 0; f < FF; f++) acc = fmaf(feat[f], W[f * DD + d], acc);

    __shared__ float red[4];
    float sq = acc * acc;
#pragma unroll
    for (int o = 16; o > 0; o >>= 1) sq += __shfl_xor_sync(0xffffffffu, sq, o);
    if ((threadIdx.x & 31) == 0) red[threadIdx.x >> 5] = sq;
    __syncthreads();
    float tot = red[0] + red[1] + red[2] + red[3];
    float nrm = fmaxf(sqrtf(tot), 1e-12f);
    g_adjx[r * DD + d] = acc / nrm;
}

// ---------------------------------------------------------------------------
// Kernel B: AX1 = adjx @ W1   (NN x 256, K=128).  NO bias (b1 added in mix).
// Block: 16 rows x 256 cols, 256 threads (thread = col, 16 row-accs).
// ---------------------------------------------------------------------------
__global__ __launch_bounds__(256) void ax1_kernel(const float* __restrict__ W1)
{
    __shared__ float sx[16][128];
    const int tid = threadIdx.x;
    const int r0 = blockIdx.x * 16;

    // load 16 adjx rows (guard past NN with zeros)
    for (int id = tid; id < 512; id += 256) {
        int r = id >> 5, q = id & 31;
        float4 v = (r0 + r < NN)
            ? *(const float4*)&g_adjx[(long)(r0 + r) * DD + q * 4]
            : make_float4(0.f, 0.f, 0.f, 0.f);
        *(float4*)&sx[r][q * 4] = v;
    }
    __syncthreads();

    float acc[16];
#pragma unroll
    for (int i = 0; i < 16; i++) acc[i] = 0.f;

    for (int k = 0; k < DD; k++) {
        float w = __ldg(&W1[(long)k * 256 + tid]);
#pragma unroll
        for (int i = 0; i < 16; i++) acc[i] = fmaf(sx[i][k], w, acc[i]);
    }

#pragma unroll
    for (int i = 0; i < 16; i++)
        if (r0 + i < NN) g_AX1[(long)(r0 + i) * 256 + tid] = acc[i];
}

// ---------------------------------------------------------------------------
// Kernel C: mix. 4 elements per block, 256 threads (64 threads/element,
// thread owns 4 contiguous columns). Per element:
//   h1[i][c] = relu(b1[c] + sum_j sub_adj[i][j] * AX1[sid[j]][c])
//   t2[r][c] = sum_i sub_adj[root_r][i] * h1[i][c]          (r = 0,1)
// The 20 gathered AX1 rows (4 cols each) live in registers (static unroll);
// sub_adj in smem, read as warp-broadcast.
// ---------------------------------------------------------------------------
__global__ __launch_bounds__(256) void mix_kernel(
    const int* __restrict__ sample_ids,
    const int* __restrict__ roots,
    const float* __restrict__ adj,
    const float* __restrict__ b1)
{
    __shared__ int   s_sid[4][SS];
    __shared__ float s_adj[4][SS][SS];
    __shared__ int   s_rt[4][2];

    const int tid = threadIdx.x;
    const int e = tid >> 6, l = tid & 63;     // element, lane-within-element
    const int b0 = blockIdx.x * 4;

    if (tid < 4 * SS) s_sid[tid / SS][tid % SS] = sample_ids[b0 * SS + tid];
    if (tid < 8) s_rt[tid >> 1][tid & 1] = roots[b0 * 2 + tid];
    __syncthreads();

    for (int id = tid; id < 4 * SS * SS; id += 256) {
        int ee = id / 400, rem = id % 400, i = rem / SS, j = rem % SS;
        s_adj[ee][i][j] =
            __ldg(&adj[(long)s_sid[ee][i] * NN + s_sid[ee][j]]);
    }
    __syncthreads();

    // gather 20 AX1 rows, 4 cols each (coalesced: 64 lanes x 16B = 1KB/row)
    float4 ax[SS];
#pragma unroll
    for (int j = 0; j < SS; j++)
        ax[j] = __ldg((const float4*)&g_AX1[(long)s_sid[e][j] * 256 + l * 4]);

    const float4 bc = __ldg((const float4*)&b1[l * 4]);
    const int r0 = s_rt[e][0], r1 = s_rt[e][1];

    float4 t0 = make_float4(0.f, 0.f, 0.f, 0.f);
    float4 t1 = make_float4(0.f, 0.f, 0.f, 0.f);

    for (int i = 0; i < SS; i++) {
        float4 h = bc;
#pragma unroll
        for (int j = 0; j < SS; j++) {
            float a = s_adj[e][i][j];
            h.x = fmaf(a, ax[j].x, h.x);
            h.y = fmaf(a, ax[j].y, h.y);
            h.z = fmaf(a, ax[j].z, h.z);
            h.w = fmaf(a, ax[j].w, h.w);
        }
        h.x = fmaxf(h.x, 0.f); h.y = fmaxf(h.y, 0.f);
        h.z = fmaxf(h.z, 0.f); h.w = fmaxf(h.w, 0.f);
        float w0 = s_adj[e][r0][i];
        float w1 = s_adj[e][r1][i];
        t0.x = fmaf(w0, h.x, t0.x); t0.y = fmaf(w0, h.y, t0.y);
        t0.z = fmaf(w0, h.z, t0.z); t0.w = fmaf(w0, h.w, t0.w);
        t1.x = fmaf(w1, h.x, t1.x); t1.y = fmaf(w1, h.y, t1.y);
        t1.z = fmaf(w1, h.z, t1.z); t1.w = fmaf(w1, h.w, t1.w);
    }

    const long base = (long)(b0 + e) * 512;
    *(float4*)&g_t2[base + l * 4]       = t0;
    *(float4*)&g_t2[base + 256 + l * 4] = t1;
}

// ---------------------------------------------------------------------------
// Kernel D: tail, 8 elements per block, 256 threads.
// ---------------------------------------------------------------------------
__global__ __launch_bounds__(256) void tail_kernel(
    const int*   __restrict__ user_idx,
    const int*   __restrict__ item_idx,
    const float* __restrict__ uid_emb,
    const float* __restrict__ sid_emb,
    const float* __restrict__ W2, const float* __restrict__ b2,
    const float* __restrict__ mW0, const float* __restrict__ mb0,
    const float* __restrict__ mW1, const float* __restrict__ mb1,
    const float* __restrict__ mW2, const float* __restrict__ mb2,
    float* __restrict__ out)
{
    __shared__ float bufA[4096];
    __shared__ float wB[8192];

    const int tid = threadIdx.x;
    const int tx = tid & 31, ty = tid >> 5;   // ty: 0..7
    const int b0 = blockIdx.x * 8;

    {
        const float4* src = (const float4*)(g_t2 + (long)b0 * 512);
        for (int id = tid; id < 1024; id += 256) ((float4*)bufA)[id] = src[id];
    }
    __syncthreads();

    // ---- ft = relu(t2 @ W2 + b2): rows er = {ty, ty+8}, cols d = tx*4+c ----
    float f[2][4] = {{0.f,0.f,0.f,0.f},{0.f,0.f,0.f,0.f}};
    for (int c0 = 0; c0 < 256; c0 += 64) {
        for (int id = tid; id < 2048; id += 256) {
            int k = id >> 5, dq = id & 31;
            *(float4*)&wB[k * 128 + dq * 4] =
                *(const float4*)&W2[(long)(c0 + k) * 128 + dq * 4];
        }
        __syncthreads();
#pragma unroll 8
        for (int kk = 0; kk < 64; kk++) {
            float4 w4 = *(const float4*)&wB[kk * 128 + tx * 4];
            float t0 = bufA[ty * 256 + c0 + kk];
            float t1 = bufA[(ty + 8) * 256 + c0 + kk];
            f[0][0] = fmaf(t0, w4.x, f[0][0]); f[0][1] = fmaf(t0, w4.y, f[0][1]);
            f[0][2] = fmaf(t0, w4.z, f[0][2]); f[0][3] = fmaf(t0, w4.w, f[0][3]);
            f[1][0] = fmaf(t1, w4.x, f[1][0]); f[1][1] = fmaf(t1, w4.y, f[1][1]);
            f[1][2] = fmaf(t1, w4.z, f[1][2]); f[1][3] = fmaf(t1, w4.w, f[1][3]);
        }
        __syncthreads();
    }

    // merge with id_vec into x at bufA[0:2048]
    {
        float4 bv = *(const float4*)&b2[tx * 4];
        float bias[4] = {bv.x, bv.y, bv.z, bv.w};
#pragma unroll
        for (int s = 0; s < 2; s++) {
            int er = ty + s * 8;
            int e = er >> 1, r = er & 1;
            const float* emb = (r == 0)
                ? &uid_emb[(long)__ldg(&user_idx[b0 + e]) * DD]
                : &sid_emb[(long)__ldg(&item_idx[b0 + e]) * DD];
            float4 idv = __ldg((const float4*)&emb[tx * 4]);
            float xv[4];
            xv[0] = 0.6f * idv.x + 0.4f * fmaxf(f[s][0] + bias[0], 0.f);
            xv[1] = 0.6f * idv.y + 0.4f * fmaxf(f[s][1] + bias[1], 0.f);
            xv[2] = 0.6f * idv.z + 0.4f * fmaxf(f[s][2] + bias[2], 0.f);
            xv[3] = 0.6f * idv.w + 0.4f * fmaxf(f[s][3] + bias[3], 0.f);
            f[s][0] = xv[0]; f[s][1] = xv[1]; f[s][2] = xv[2]; f[s][3] = xv[3];
        }
    }
    __syncthreads();
#pragma unroll
    for (int s = 0; s < 2; s++) {
        int er = ty + s * 8;
        int e = er >> 1, r = er & 1;
        *(float4*)&bufA[e * 256 + r * 128 + tx * 4] = *(float4*)&f[s][0];
    }
    __syncthreads();

    // ---- MLP0: y1 = relu(x @ mW0 + mb0) ----
    float g0[4] = {0.f, 0.f, 0.f, 0.f};
    for (int c0 = 0; c0 < 256; c0 += 64) {
        for (int id = tid; id < 2048; id += 256) {
            int k = id >> 5, dq = id & 31;
            *(float4*)&wB[k * 128 + dq * 4] =
                *(const float4*)&mW0[(long)(c0 + k) * 128 + dq * 4];
        }
        __syncthreads();
#pragma unroll 8
        for (int kk = 0; kk < 64; kk++) {
            float4 w4 = *(const float4*)&wB[kk * 128 + tx * 4];
            float xv = bufA[ty * 256 + c0 + kk];
            g0[0] = fmaf(xv, w4.x, g0[0]); g0[1] = fmaf(xv, w4.y, g0[1]);
            g0[2] = fmaf(xv, w4.z, g0[2]); g0[3] = fmaf(xv, w4.w, g0[3]);
        }
        __syncthreads();
    }
    {
        float4 bv = __ldg((const float4*)&mb0[tx * 4]);
        float4 y;
        y.x = fmaxf(g0[0] + bv.x, 0.f); y.y = fmaxf(g0[1] + bv.y, 0.f);
        y.z = fmaxf(g0[2] + bv.z, 0.f); y.w = fmaxf(g0[3] + bv.w, 0.f);
        *(float4*)&bufA[2048 + ty * 128 + tx * 4] = y;
    }
    for (int id = tid; id < 2048; id += 256)
        ((float4*)wB)[id] = __ldg(&((const float4*)mW1)[id]);
    __syncthreads();

    // ---- MLP1 ----
    {
        int oo = tx * 2;
        float a0 = 0.f, a1 = 0.f;
#pragma unroll 4
        for (int k = 0; k < 128; k++) {
            float yv = bufA[2048 + ty * 128 + k];
            float2 w2 = *(const float2*)&wB[k * 64 + oo];
            a0 = fmaf(yv, w2.x, a0);
            a1 = fmaf(yv, w2.y, a1);
        }
        float2 bv = __ldg((const float2*)&mb1[oo]);
        bufA[3072 + ty * 64 + oo]     = fmaxf(a0 + bv.x, 0.f);
        bufA[3072 + ty * 64 + oo + 1] = fmaxf(a1 + bv.y, 0.f);
    }
    __syncthreads();

    // ---- MLP2 ----
    {
        float p = bufA[3072 + ty * 64 + tx] * __ldg(&mW2[tx]) +
                  bufA[3072 + ty * 64 + 32 + tx] * __ldg(&mW2[32 + tx]);
#pragma unroll
        for (int o = 16; o > 0; o >>= 1) p += __shfl_xor_sync(0xffffffffu, p, o);
        if (tx == 0) out[b0 + ty] = fmaxf(p + __ldg(&mb2[0]), 0.f);
    }
}

// ---------------------------------------------------------------------------
extern "C" void kernel_launch(void* const* d_in, const int* in_sizes, int n_in,
                              void* d_out, int out_size)
{
    const int*   user_indexes = (const int*)  d_in[0];
    const int*   item_indexes = (const int*)  d_in[1];
    const int*   sample_ids   = (const int*)  d_in[2];
    const int*   roots        = (const int*)  d_in[3];
    const float* user_infos   = (const float*)d_in[4];
    const float* item_infos   = (const float*)d_in[5];
    const float* adj_matrix   = (const float*)d_in[6];
    const float* uid_emb      = (const float*)d_in[7];
    const float* sid_emb      = (const float*)d_in[8];
    const float* Wu           = (const float*)d_in[9];
    const float* bu           = (const float*)d_in[10];
    const float* Wi           = (const float*)d_in[11];
    const float* bi           = (const float*)d_in[12];
    const float* W1           = (const float*)d_in[13];
    const float* b1           = (const float*)d_in[14];
    const float* W2           = (const float*)d_in[15];
    const float* b2           = (const float*)d_in[16];
    const float* mW0          = (const float*)d_in[17];
    const float* mb0          = (const float*)d_in[18];
    const float* mW1          = (const float*)d_in[19];
    const float* mb1          = (const float*)d_in[20];
    const float* mW2          = (const float*)d_in[21];
    const float* mb2          = (const float*)d_in[22];
    float* out = (float*)d_out;

    adjx_kernel<<<NN, DD>>>(user_infos, item_infos, Wu, bu, Wi, bi);
    ax1_kernel<<<(NN + 15) / 16, 256>>>(W1);
    mix_kernel<<<BB / 4, 256>>>(sample_ids, roots, adj_matrix, b1);
    tail_kernel<<<BB / 8, 256>>>(user_indexes, item_indexes, uid_emb, sid_emb,
                                 W2, b2, mW0, mb0, mW1, mb1, mW2, mb2,
                                 out);
}

// round 10
// speedup vs baseline: 5.0810x; 1.2286x over previous
#include <cuda_runtime.h>
#include <cuda_bf16.h>

#define NU 339
#define NI 5825
#define NN 6164          // NU + NI
#define BB 32768
#define SS 20
#define DD 128
#define FF 8

// Scratch (device globals: allocation-free per harness rules)
__device__ float g_adjx[NN * DD];                  // 3.2 MB
__device__ float g_AX1[NN * 2 * DD];               // 6.3 MB (L2-resident)
__device__ float g_t2[(size_t)BB * 2 * 256];       // 67 MB

// ---------------------------------------------------------------------------
// Kernel A: adj_x = l2norm(user_infos@Wu + bu) ++ l2norm(item_infos@Wi + bi)
// ---------------------------------------------------------------------------
__global__ __launch_bounds__(DD) void adjx_kernel(
    const float* __restrict__ user_infos, const float* __restrict__ item_infos,
    const float* __restrict__ Wu, const float* __restrict__ bu,
    const float* __restrict__ Wi, const float* __restrict__ bi)
{
    int r = blockIdx.x;
    int d = threadIdx.x;
    const float* feat;
    const float* W;
    const float* bv;
    if (r < NU) { feat = user_infos + r * FF;        W = Wu; bv = bu; }
    else        { feat = item_infos + (r - NU) * FF; W = Wi; bv = bi; }

    float acc = bv[d];
#pragma unroll
    for (int f = 0; f < FF; f++) acc = fmaf(feat[f], W[f * DD + d], acc);

    __shared__ float red[4];
    float sq = acc * acc;
#pragma unroll
    for (int o = 16; o > 0; o >>= 1) sq += __shfl_xor_sync(0xffffffffu, sq, o);
    if ((threadIdx.x & 31) == 0) red[threadIdx.x >> 5] = sq;
    __syncthreads();
    float tot = red[0] + red[1] + red[2] + red[3];
    float nrm = fmaxf(sqrtf(tot), 1e-12f);
    g_adjx[r * DD + d] = acc / nrm;
}

// ---------------------------------------------------------------------------
// Kernel B: AX1 = adjx @ W1   (NN x 256, K=128).  NO bias (b1 added in mix).
// ---------------------------------------------------------------------------
__global__ __launch_bounds__(256) void ax1_kernel(const float* __restrict__ W1)
{
    __shared__ float sx[16][128];
    const int tid = threadIdx.x;
    const int r0 = blockIdx.x * 16;

    for (int id = tid; id < 512; id += 256) {
        int r = id >> 5, q = id & 31;
        float4 v = (r0 + r < NN)
            ? *(const float4*)&g_adjx[(long)(r0 + r) * DD + q * 4]
            : make_float4(0.f, 0.f, 0.f, 0.f);
        *(float4*)&sx[r][q * 4] = v;
    }
    __syncthreads();

    float acc[16];
#pragma unroll
    for (int i = 0; i < 16; i++) acc[i] = 0.f;

    for (int k = 0; k < DD; k++) {
        float w = __ldg(&W1[(long)k * 256 + tid]);
#pragma unroll
        for (int i = 0; i < 16; i++) acc[i] = fmaf(sx[i][k], w, acc[i]);
    }

#pragma unroll
    for (int i = 0; i < 16; i++)
        if (r0 + i < NN) g_AX1[(long)(r0 + i) * 256 + tid] = acc[i];
}

// ---------------------------------------------------------------------------
// Kernel C: mix. 4 elements per block, 256 threads (64 threads/element,
// thread owns 4 contiguous columns).
//   h1[i][c] = relu(b1[c] + sum_j sub_adj[i][j] * AX1[sid[j]][c])
//   t2[r][c] = sum_i sub_adj[root_r][i] * h1[i][c]
// ---------------------------------------------------------------------------
__global__ __launch_bounds__(256) void mix_kernel(
    const int* __restrict__ sample_ids,
    const int* __restrict__ roots,
    const float* __restrict__ adj,
    const float* __restrict__ b1)
{
    __shared__ int   s_sid[4][SS];
    __shared__ float s_adj[4][SS][SS];
    __shared__ int   s_rt[4][2];

    const int tid = threadIdx.x;
    const int e = tid >> 6, l = tid & 63;
    const int b0 = blockIdx.x * 4;

    if (tid < 4 * SS) s_sid[tid / SS][tid % SS] = sample_ids[b0 * SS + tid];
    if (tid < 8) s_rt[tid >> 1][tid & 1] = roots[b0 * 2 + tid];
    __syncthreads();

    for (int id = tid; id < 4 * SS * SS; id += 256) {
        int ee = id / 400, rem = id % 400, i = rem / SS, j = rem % SS;
        s_adj[ee][i][j] =
            __ldg(&adj[(long)s_sid[ee][i] * NN + s_sid[ee][j]]);
    }
    __syncthreads();

    float4 ax[SS];
#pragma unroll
    for (int j = 0; j < SS; j++)
        ax[j] = __ldg((const float4*)&g_AX1[(long)s_sid[e][j] * 256 + l * 4]);

    const float4 bc = __ldg((const float4*)&b1[l * 4]);
    const int r0 = s_rt[e][0], r1 = s_rt[e][1];

    float4 t0 = make_float4(0.f, 0.f, 0.f, 0.f);
    float4 t1 = make_float4(0.f, 0.f, 0.f, 0.f);

    for (int i = 0; i < SS; i++) {
        float4 h = bc;
#pragma unroll
        for (int j = 0; j < SS; j++) {
            float a = s_adj[e][i][j];
            h.x = fmaf(a, ax[j].x, h.x);
            h.y = fmaf(a, ax[j].y, h.y);
            h.z = fmaf(a, ax[j].z, h.z);
            h.w = fmaf(a, ax[j].w, h.w);
        }
        h.x = fmaxf(h.x, 0.f); h.y = fmaxf(h.y, 0.f);
        h.z = fmaxf(h.z, 0.f); h.w = fmaxf(h.w, 0.f);
        float w0 = s_adj[e][r0][i];
        float w1 = s_adj[e][r1][i];
        t0.x = fmaf(w0, h.x, t0.x); t0.y = fmaf(w0, h.y, t0.y);
        t0.z = fmaf(w0, h.z, t0.z); t0.w = fmaf(w0, h.w, t0.w);
        t1.x = fmaf(w1, h.x, t1.x); t1.y = fmaf(w1, h.y, t1.y);
        t1.z = fmaf(w1, h.z, t1.z); t1.w = fmaf(w1, h.w, t1.w);
    }

    const long base = (long)(b0 + e) * 512;
    *(float4*)&g_t2[base + l * 4]       = t0;
    *(float4*)&g_t2[base + 256 + l * 4] = t1;
}

// ---------------------------------------------------------------------------
// Kernel D: tail, 16 elements per block, 256 threads. grid = BB/16.
// smem: bufA[8192] = t2 (32x256); later x[0:4096], y1[4096:6144], y2[6144:7168]
//       wB[4096]   = 32-row K-chunks of W2 / mW0 / mW1
// Thread map: tx = tid&31 (4 cols), ty = tid>>5 (0..7).
// ---------------------------------------------------------------------------
__global__ __launch_bounds__(256) void tail_kernel(
    const int*   __restrict__ user_idx,
    const int*   __restrict__ item_idx,
    const float* __restrict__ uid_emb,
    const float* __restrict__ sid_emb,
    const float* __restrict__ W2, const float* __restrict__ b2,
    const float* __restrict__ mW0, const float* __restrict__ mb0,
    const float* __restrict__ mW1, const float* __restrict__ mb1,
    const float* __restrict__ mW2, const float* __restrict__ mb2,
    float* __restrict__ out)
{
    __shared__ float bufA[8192];
    __shared__ float wB[4096];

    const int tid = threadIdx.x;
    const int tx = tid & 31, ty = tid >> 5;
    const int b0 = blockIdx.x * 16;

    // load t2 for 16 elements (8192 floats, contiguous)
    {
        const float4* src = (const float4*)(g_t2 + (long)b0 * 512);
        for (int id = tid; id < 2048; id += 256) ((float4*)bufA)[id] = src[id];
    }
    __syncthreads();

    // ---- ft = t2 @ W2: 32 rows (er = ty+8s) x 128 cols (tx*4..+3), K=256 ----
    float f[4][4];
#pragma unroll
    for (int s = 0; s < 4; s++)
#pragma unroll
        for (int c = 0; c < 4; c++) f[s][c] = 0.f;

    for (int c0 = 0; c0 < 256; c0 += 32) {
        for (int id = tid; id < 1024; id += 256) {
            int k = id >> 5, dq = id & 31;
            *(float4*)&wB[k * 128 + dq * 4] =
                *(const float4*)&W2[(long)(c0 + k) * 128 + dq * 4];
        }
        __syncthreads();
#pragma unroll 8
        for (int kk = 0; kk < 32; kk++) {
            float4 w4 = *(const float4*)&wB[kk * 128 + tx * 4];
#pragma unroll
            for (int s = 0; s < 4; s++) {
                float t = bufA[(ty + 8 * s) * 256 + c0 + kk];
                f[s][0] = fmaf(t, w4.x, f[s][0]);
                f[s][1] = fmaf(t, w4.y, f[s][1]);
                f[s][2] = fmaf(t, w4.z, f[s][2]);
                f[s][3] = fmaf(t, w4.w, f[s][3]);
            }
        }
        __syncthreads();
    }

    // ---- merge with id_vec: x[e][r*128+d] = 0.6*emb + 0.4*relu(f + b2) ----
    {
        float4 bv = *(const float4*)&b2[tx * 4];
#pragma unroll
        for (int s = 0; s < 4; s++) {
            int er = ty + 8 * s;
            int e = er >> 1, r = er & 1;
            const float* emb = (r == 0)
                ? &uid_emb[(long)__ldg(&user_idx[b0 + e]) * DD]
                : &sid_emb[(long)__ldg(&item_idx[b0 + e]) * DD];
            float4 idv = __ldg((const float4*)&emb[tx * 4]);
            f[s][0] = 0.6f * idv.x + 0.4f * fmaxf(f[s][0] + bv.x, 0.f);
            f[s][1] = 0.6f * idv.y + 0.4f * fmaxf(f[s][1] + bv.y, 0.f);
            f[s][2] = 0.6f * idv.z + 0.4f * fmaxf(f[s][2] + bv.z, 0.f);
            f[s][3] = 0.6f * idv.w + 0.4f * fmaxf(f[s][3] + bv.w, 0.f);
        }
    }
    __syncthreads();   // all t2 reads done; safe to overwrite bufA[0:4096)
#pragma unroll
    for (int s = 0; s < 4; s++) {
        int er = ty + 8 * s;
        int e = er >> 1, r = er & 1;
        *(float4*)&bufA[e * 256 + r * 128 + tx * 4] = *(float4*)&f[s][0];
    }
    __syncthreads();

    // ---- MLP0: y1 = relu(x @ mW0 + mb0): elems {ty, ty+8}, cols tx*4 ----
    float g0[2][4];
#pragma unroll
    for (int s = 0; s < 2; s++)
#pragma unroll
        for (int c = 0; c < 4; c++) g0[s][c] = 0.f;

    for (int c0 = 0; c0 < 256; c0 += 32) {
        for (int id = tid; id < 1024; id += 256) {
            int k = id >> 5, dq = id & 31;
            *(float4*)&wB[k * 128 + dq * 4] =
                *(const float4*)&mW0[(long)(c0 + k) * 128 + dq * 4];
        }
        __syncthreads();
#pragma unroll 8
        for (int kk = 0; kk < 32; kk++) {
            float4 w4 = *(const float4*)&wB[kk * 128 + tx * 4];
            float x0 = bufA[ty * 256 + c0 + kk];
            float x1 = bufA[(ty + 8) * 256 + c0 + kk];
            g0[0][0] = fmaf(x0, w4.x, g0[0][0]); g0[0][1] = fmaf(x0, w4.y, g0[0][1]);
            g0[0][2] = fmaf(x0, w4.z, g0[0][2]); g0[0][3] = fmaf(x0, w4.w, g0[0][3]);
            g0[1][0] = fmaf(x1, w4.x, g0[1][0]); g0[1][1] = fmaf(x1, w4.y, g0[1][1]);
            g0[1][2] = fmaf(x1, w4.z, g0[1][2]); g0[1][3] = fmaf(x1, w4.w, g0[1][3]);
        }
        __syncthreads();
    }
    {
        float4 bv = __ldg((const float4*)&mb0[tx * 4]);
#pragma unroll
        for (int s = 0; s < 2; s++) {
            int e = ty + 8 * s;
            float4 y;
            y.x = fmaxf(g0[s][0] + bv.x, 0.f); y.y = fmaxf(g0[s][1] + bv.y, 0.f);
            y.z = fmaxf(g0[s][2] + bv.z, 0.f); y.w = fmaxf(g0[s][3] + bv.w, 0.f);
            *(float4*)&bufA[4096 + e * 128 + tx * 4] = y;   // y1[e][128]
        }
    }
    __syncthreads();

    // ---- MLP1: y2 = relu(y1 @ mW1 + mb1): elems {ty, ty+8}, cols tx*2 ----
    {
        const int oo = tx * 2;
        float a00 = 0.f, a01 = 0.f, a10 = 0.f, a11 = 0.f;
        for (int c0 = 0; c0 < 128; c0 += 64) {
            // load mW1 rows c0..c0+63 (64 x 64 = 4096 floats)
            for (int id = tid; id < 1024; id += 256) {
                int k = id >> 4, dq = id & 15;
                *(float4*)&wB[k * 64 + dq * 4] =
                    *(const float4*)&mW1[(long)(c0 + k) * 64 + dq * 4];
            }
            __syncthreads();
#pragma unroll 8
            for (int kk = 0; kk < 64; kk++) {
                float2 w2 = *(const float2*)&wB[kk * 64 + oo];
                float y0 = bufA[4096 + ty * 128 + c0 + kk];
                float y1v = bufA[4096 + (ty + 8) * 128 + c0 + kk];
                a00 = fmaf(y0, w2.x, a00);  a01 = fmaf(y0, w2.y, a01);
                a10 = fmaf(y1v, w2.x, a10); a11 = fmaf(y1v, w2.y, a11);
            }
            __syncthreads();
        }
        float2 bv = __ldg((const float2*)&mb1[oo]);
        bufA[6144 + ty * 64 + oo]            = fmaxf(a00 + bv.x, 0.f);
        bufA[6144 + ty * 64 + oo + 1]        = fmaxf(a01 + bv.y, 0.f);
        bufA[6144 + (ty + 8) * 64 + oo]      = fmaxf(a10 + bv.x, 0.f);
        bufA[6144 + (ty + 8) * 64 + oo + 1]  = fmaxf(a11 + bv.y, 0.f);
    }
    __syncthreads();

    // ---- MLP2: warp ty handles elements ty and ty+8 ----
    {
        float wlo = __ldg(&mW2[tx]);
        float whi = __ldg(&mW2[32 + tx]);
        float bias = __ldg(&mb2[0]);
#pragma unroll
        for (int s = 0; s < 2; s++) {
            int e = ty + 8 * s;
            float p = bufA[6144 + e * 64 + tx] * wlo +
                      bufA[6144 + e * 64 + 32 + tx] * whi;
#pragma unroll
            for (int o = 16; o > 0; o >>= 1)
                p += __shfl_xor_sync(0xffffffffu, p, o);
            if (tx == 0) out[b0 + e] = fmaxf(p + bias, 0.f);
        }
    }
}

// ---------------------------------------------------------------------------
extern "C" void kernel_launch(void* const* d_in, const int* in_sizes, int n_in,
                              void* d_out, int out_size)
{
    const int*   user_indexes = (const int*)  d_in[0];
    const int*   item_indexes = (const int*)  d_in[1];
    const int*   sample_ids   = (const int*)  d_in[2];
    const int*   roots        = (const int*)  d_in[3];
    const float* user_infos   = (const float*)d_in[4];
    const float* item_infos   = (const float*)d_in[5];
    const float* adj_matrix   = (const float*)d_in[6];
    const float* uid_emb      = (const float*)d_in[7];
    const float* sid_emb      = (const float*)d_in[8];
    const float* Wu           = (const float*)d_in[9];
    const float* bu           = (const float*)d_in[10];
    const float* Wi           = (const float*)d_in[11];
    const float* bi           = (const float*)d_in[12];
    const float* W1           = (const float*)d_in[13];
    const float* b1           = (const float*)d_in[14];
    const float* W2           = (const float*)d_in[15];
    const float* b2           = (const float*)d_in[16];
    const float* mW0          = (const float*)d_in[17];
    const float* mb0          = (const float*)d_in[18];
    const float* mW1          = (const float*)d_in[19];
    const float* mb1          = (const float*)d_in[20];
    const float* mW2          = (const float*)d_in[21];
    const float* mb2          = (const float*)d_in[22];
    float* out = (float*)d_out;

    adjx_kernel<<<NN, DD>>>(user_infos, item_infos, Wu, bu, Wi, bi);
    ax1_kernel<<<(NN + 15) / 16, 256>>>(W1);
    mix_kernel<<<BB / 4, 256>>>(sample_ids, roots, adj_matrix, b1);
    tail_kernel<<<BB / 16, 256>>>(user_indexes, item_indexes, uid_emb, sid_emb,
                                  W2, b2, mW0, mb0, mW1, mb1, mW2, mb2,
                                  out);
}

// round 11
// speedup vs baseline: 5.6938x; 1.1206x over previous
#include <cuda_runtime.h>
#include <cuda_bf16.h>

#define NU 339
#define NI 5825
#define NN 6164          // NU + NI
#define BB 32768
#define SS 20
#define DD 128
#define FF 8

// Scratch (device globals: allocation-free per harness rules)
__device__ float g_adjx[NN * DD];                  // 3.2 MB
__device__ float g_AX1[NN * 2 * DD];               // 6.3 MB (L2-resident)
__device__ float g_t2[(size_t)BB * 2 * 256];       // 67 MB

// ---------------------------------------------------------------------------
// Kernel A: adj_x = l2norm(user_infos@Wu + bu) ++ l2norm(item_infos@Wi + bi)
// ---------------------------------------------------------------------------
__global__ __launch_bounds__(DD) void adjx_kernel(
    const float* __restrict__ user_infos, const float* __restrict__ item_infos,
    const float* __restrict__ Wu, const float* __restrict__ bu,
    const float* __restrict__ Wi, const float* __restrict__ bi)
{
    int r = blockIdx.x;
    int d = threadIdx.x;
    const float* feat;
    const float* W;
    const float* bv;
    if (r < NU) { feat = user_infos + r * FF;        W = Wu; bv = bu; }
    else        { feat = item_infos + (r - NU) * FF; W = Wi; bv = bi; }

    float acc = bv[d];
#pragma unroll
    for (int f = 0; f < FF; f++) acc = fmaf(feat[f], W[f * DD + d], acc);

    __shared__ float red[4];
    float sq = acc * acc;
#pragma unroll
    for (int o = 16; o > 0; o >>= 1) sq += __shfl_xor_sync(0xffffffffu, sq, o);
    if ((threadIdx.x & 31) == 0) red[threadIdx.x >> 5] = sq;
    __syncthreads();
    float tot = red[0] + red[1] + red[2] + red[3];
    float nrm = fmaxf(sqrtf(tot), 1e-12f);
    g_adjx[r * DD + d] = acc / nrm;
}

// ---------------------------------------------------------------------------
// Kernel B: AX1 = adjx @ W1   (NN x 256, K=128).  NO bias (b1 added in mix).
// ---------------------------------------------------------------------------
__global__ __launch_bounds__(256) void ax1_kernel(const float* __restrict__ W1)
{
    __shared__ float sx[16][128];
    const int tid = threadIdx.x;
    const int r0 = blockIdx.x * 16;

    for (int id = tid; id < 512; id += 256) {
        int r = id >> 5, q = id & 31;
        float4 v = (r0 + r < NN)
            ? *(const float4*)&g_adjx[(long)(r0 + r) * DD + q * 4]
            : make_float4(0.f, 0.f, 0.f, 0.f);
        *(float4*)&sx[r][q * 4] = v;
    }
    __syncthreads();

    float acc[16];
#pragma unroll
    for (int i = 0; i < 16; i++) acc[i] = 0.f;

    for (int k = 0; k < DD; k++) {
        float w = __ldg(&W1[(long)k * 256 + tid]);
#pragma unroll
        for (int i = 0; i < 16; i++) acc[i] = fmaf(sx[i][k], w, acc[i]);
    }

#pragma unroll
    for (int i = 0; i < 16; i++)
        if (r0 + i < NN) g_AX1[(long)(r0 + i) * 256 + tid] = acc[i];
}

// ---------------------------------------------------------------------------
// Kernel C: mix. 2 elements per block, 128 threads/element, thread owns 2
// contiguous columns (low reg pressure -> 3-4 blocks/SM).
//   h1[i][c] = relu(b1[c] + sum_j sub_adj[i][j] * AX1[sid[j]][c])
//   t2[r][c] = sum_i sub_adj[root_r][i] * h1[i][c]
// ---------------------------------------------------------------------------
__global__ __launch_bounds__(256) void mix_kernel(
    const int* __restrict__ sample_ids,
    const int* __restrict__ roots,
    const float* __restrict__ adj,
    const float* __restrict__ b1)
{
    __shared__ int   s_sid[2][SS];
    __shared__ float s_adj[2][SS][SS];
    __shared__ int   s_rt[2][2];

    const int tid = threadIdx.x;
    const int e = tid >> 7, l = tid & 127;
    const int b0 = blockIdx.x * 2;

    if (tid < 2 * SS) s_sid[tid / SS][tid % SS] = sample_ids[b0 * SS + tid];
    if (tid < 4) s_rt[tid >> 1][tid & 1] = roots[b0 * 2 + tid];
    __syncthreads();

    for (int id = tid; id < 2 * SS * SS; id += 256) {
        int ee = id / 400, rem = id % 400, i = rem / SS, j = rem % SS;
        s_adj[ee][i][j] =
            __ldg(&adj[(long)s_sid[ee][i] * NN + s_sid[ee][j]]);
    }
    __syncthreads();

    // gather 20 AX1 rows, 2 cols each (coalesced: 128 lanes x 8B = 1KB/row)
    float2 ax[SS];
#pragma unroll
    for (int j = 0; j < SS; j++)
        ax[j] = __ldg((const float2*)&g_AX1[(long)s_sid[e][j] * 256 + l * 2]);

    const float2 bc = __ldg((const float2*)&b1[l * 2]);
    const int r0 = s_rt[e][0], r1 = s_rt[e][1];

    float2 t0 = make_float2(0.f, 0.f);
    float2 t1 = make_float2(0.f, 0.f);

#pragma unroll 2
    for (int i = 0; i < SS; i++) {
        float2 h = bc;
#pragma unroll
        for (int j = 0; j < SS; j++) {
            float a = s_adj[e][i][j];
            h.x = fmaf(a, ax[j].x, h.x);
            h.y = fmaf(a, ax[j].y, h.y);
        }
        h.x = fmaxf(h.x, 0.f);
        h.y = fmaxf(h.y, 0.f);
        float w0 = s_adj[e][r0][i];
        float w1 = s_adj[e][r1][i];
        t0.x = fmaf(w0, h.x, t0.x); t0.y = fmaf(w0, h.y, t0.y);
        t1.x = fmaf(w1, h.x, t1.x); t1.y = fmaf(w1, h.y, t1.y);
    }

    const long base = (long)(b0 + e) * 512;
    *(float2*)&g_t2[base + l * 2]       = t0;
    *(float2*)&g_t2[base + 256 + l * 2] = t1;
}

// ---------------------------------------------------------------------------
// Kernel D: tail, 16 elements per block, 256 threads. grid = BB/16.
// K-by-4 vectorized microkernels (float4 activation loads) to cut smem
// wavefronts per FMA.
// smem: bufA[8192] = t2 (32x256); later x[0:4096], y1[4096:6144], y2[6144:7168]
//       wB[4096]   = 32-row K-chunks of W2 / mW0 / 64-row chunks of mW1
// ---------------------------------------------------------------------------
__global__ __launch_bounds__(256) void tail_kernel(
    const int*   __restrict__ user_idx,
    const int*   __restrict__ item_idx,
    const float* __restrict__ uid_emb,
    const float* __restrict__ sid_emb,
    const float* __restrict__ W2, const float* __restrict__ b2,
    const float* __restrict__ mW0, const float* __restrict__ mb0,
    const float* __restrict__ mW1, const float* __restrict__ mb1,
    const float* __restrict__ mW2, const float* __restrict__ mb2,
    float* __restrict__ out)
{
    __shared__ float bufA[8192];
    __shared__ float wB[4096];

    const int tid = threadIdx.x;
    const int tx = tid & 31, ty = tid >> 5;
    const int b0 = blockIdx.x * 16;

    // load t2 for 16 elements (8192 floats, contiguous)
    {
        const float4* src = (const float4*)(g_t2 + (long)b0 * 512);
        for (int id = tid; id < 2048; id += 256) ((float4*)bufA)[id] = src[id];
    }
    __syncthreads();

    // ---- ft = t2 @ W2: 32 rows (er = ty+8s) x 128 cols (tx*4..+3), K=256 ----
    float f[4][4];
#pragma unroll
    for (int s = 0; s < 4; s++)
#pragma unroll
        for (int c = 0; c < 4; c++) f[s][c] = 0.f;

    for (int c0 = 0; c0 < 256; c0 += 32) {
        for (int id = tid; id < 1024; id += 256) {
            int k = id >> 5, dq = id & 31;
            *(float4*)&wB[k * 128 + dq * 4] =
                *(const float4*)&W2[(long)(c0 + k) * 128 + dq * 4];
        }
        __syncthreads();
#pragma unroll
        for (int kk4 = 0; kk4 < 8; kk4++) {
            float4 tv[4];
#pragma unroll
            for (int s = 0; s < 4; s++)
                tv[s] = *(const float4*)&bufA[(ty + 8 * s) * 256 + c0 + kk4 * 4];
#pragma unroll
            for (int u = 0; u < 4; u++) {
                float4 w4 = *(const float4*)&wB[(kk4 * 4 + u) * 128 + tx * 4];
#pragma unroll
                for (int s = 0; s < 4; s++) {
                    float t = ((const float*)&tv[s])[u];
                    f[s][0] = fmaf(t, w4.x, f[s][0]);
                    f[s][1] = fmaf(t, w4.y, f[s][1]);
                    f[s][2] = fmaf(t, w4.z, f[s][2]);
                    f[s][3] = fmaf(t, w4.w, f[s][3]);
                }
            }
        }
        __syncthreads();
    }

    // ---- merge with id_vec: x[e][r*128+d] = 0.6*emb + 0.4*relu(f + b2) ----
    {
        float4 bv = *(const float4*)&b2[tx * 4];
#pragma unroll
        for (int s = 0; s < 4; s++) {
            int er = ty + 8 * s;
            int e = er >> 1, r = er & 1;
            const float* emb = (r == 0)
                ? &uid_emb[(long)__ldg(&user_idx[b0 + e]) * DD]
                : &sid_emb[(long)__ldg(&item_idx[b0 + e]) * DD];
            float4 idv = __ldg((const float4*)&emb[tx * 4]);
            f[s][0] = 0.6f * idv.x + 0.4f * fmaxf(f[s][0] + bv.x, 0.f);
            f[s][1] = 0.6f * idv.y + 0.4f * fmaxf(f[s][1] + bv.y, 0.f);
            f[s][2] = 0.6f * idv.z + 0.4f * fmaxf(f[s][2] + bv.z, 0.f);
            f[s][3] = 0.6f * idv.w + 0.4f * fmaxf(f[s][3] + bv.w, 0.f);
        }
    }
    __syncthreads();   // all t2 reads done; safe to overwrite bufA[0:4096)
#pragma unroll
    for (int s = 0; s < 4; s++) {
        int er = ty + 8 * s;
        int e = er >> 1, r = er & 1;
        *(float4*)&bufA[e * 256 + r * 128 + tx * 4] = *(float4*)&f[s][0];
    }
    __syncthreads();

    // ---- MLP0: y1 = relu(x @ mW0 + mb0): elems {ty, ty+8}, cols tx*4 ----
    float g0[2][4];
#pragma unroll
    for (int s = 0; s < 2; s++)
#pragma unroll
        for (int c = 0; c < 4; c++) g0[s][c] = 0.f;

    for (int c0 = 0; c0 < 256; c0 += 32) {
        for (int id = tid; id < 1024; id += 256) {
            int k = id >> 5, dq = id & 31;
            *(float4*)&wB[k * 128 + dq * 4] =
                *(const float4*)&mW0[(long)(c0 + k) * 128 + dq * 4];
        }
        __syncthreads();
#pragma unroll
        for (int kk4 = 0; kk4 < 8; kk4++) {
            float4 xv0 = *(const float4*)&bufA[ty * 256 + c0 + kk4 * 4];
            float4 xv1 = *(const float4*)&bufA[(ty + 8) * 256 + c0 + kk4 * 4];
#pragma unroll
            for (int u = 0; u < 4; u++) {
                float4 w4 = *(const float4*)&wB[(kk4 * 4 + u) * 128 + tx * 4];
                float x0 = ((const float*)&xv0)[u];
                float x1 = ((const float*)&xv1)[u];
                g0[0][0] = fmaf(x0, w4.x, g0[0][0]); g0[0][1] = fmaf(x0, w4.y, g0[0][1]);
                g0[0][2] = fmaf(x0, w4.z, g0[0][2]); g0[0][3] = fmaf(x0, w4.w, g0[0][3]);
                g0[1][0] = fmaf(x1, w4.x, g0[1][0]); g0[1][1] = fmaf(x1, w4.y, g0[1][1]);
                g0[1][2] = fmaf(x1, w4.z, g0[1][2]); g0[1][3] = fmaf(x1, w4.w, g0[1][3]);
            }
        }
        __syncthreads();
    }
    {
        float4 bv = __ldg((const float4*)&mb0[tx * 4]);
#pragma unroll
        for (int s = 0; s < 2; s++) {
            int e = ty + 8 * s;
            float4 y;
            y.x = fmaxf(g0[s][0] + bv.x, 0.f); y.y = fmaxf(g0[s][1] + bv.y, 0.f);
            y.z = fmaxf(g0[s][2] + bv.z, 0.f); y.w = fmaxf(g0[s][3] + bv.w, 0.f);
            *(float4*)&bufA[4096 + e * 128 + tx * 4] = y;   // y1[e][128]
        }
    }
    __syncthreads();

    // ---- MLP1: y2 = relu(y1 @ mW1 + mb1): elems {ty, ty+8}, cols tx*2 ----
    {
        const int oo = tx * 2;
        float a00 = 0.f, a01 = 0.f, a10 = 0.f, a11 = 0.f;
        for (int c0 = 0; c0 < 128; c0 += 64) {
            // load mW1 rows c0..c0+63 (64 x 64 = 4096 floats)
            for (int id = tid; id < 1024; id += 256) {
                int k = id >> 4, dq = id & 15;
                *(float4*)&wB[k * 64 + dq * 4] =
                    *(const float4*)&mW1[(long)(c0 + k) * 64 + dq * 4];
            }
            __syncthreads();
#pragma unroll
            for (int kk4 = 0; kk4 < 16; kk4++) {
                float4 yv0 = *(const float4*)&bufA[4096 + ty * 128 + c0 + kk4 * 4];
                float4 yv1 = *(const float4*)&bufA[4096 + (ty + 8) * 128 + c0 + kk4 * 4];
#pragma unroll
                for (int u = 0; u < 4; u++) {
                    float2 w2 = *(const float2*)&wB[(kk4 * 4 + u) * 64 + oo];
                    float y0 = ((const float*)&yv0)[u];
                    float y1v = ((const float*)&yv1)[u];
                    a00 = fmaf(y0, w2.x, a00);  a01 = fmaf(y0, w2.y, a01);
                    a10 = fmaf(y1v, w2.x, a10); a11 = fmaf(y1v, w2.y, a11);
                }
            }
            __syncthreads();
        }
        float2 bv = __ldg((const float2*)&mb1[oo]);
        bufA[6144 + ty * 64 + oo]            = fmaxf(a00 + bv.x, 0.f);
        bufA[6144 + ty * 64 + oo + 1]        = fmaxf(a01 + bv.y, 0.f);
        bufA[6144 + (ty + 8) * 64 + oo]      = fmaxf(a10 + bv.x, 0.f);
        bufA[6144 + (ty + 8) * 64 + oo + 1]  = fmaxf(a11 + bv.y, 0.f);
    }
    __syncthreads();

    // ---- MLP2: warp ty handles elements ty and ty+8 ----
    {
        float wlo = __ldg(&mW2[tx]);
        float whi = __ldg(&mW2[32 + tx]);
        float bias = __ldg(&mb2[0]);
#pragma unroll
        for (int s = 0; s < 2; s++) {
            int e = ty + 8 * s;
            float p = bufA[6144 + e * 64 + tx] * wlo +
                      bufA[6144 + e * 64 + 32 + tx] * whi;
#pragma unroll
            for (int o = 16; o > 0; o >>= 1)
                p += __shfl_xor_sync(0xffffffffu, p, o);
            if (tx == 0) out[b0 + e] = fmaxf(p + bias, 0.f);
        }
    }
}

// ---------------------------------------------------------------------------
extern "C" void kernel_launch(void* const* d_in, const int* in_sizes, int n_in,
                              void* d_out, int out_size)
{
    const int*   user_indexes = (const int*)  d_in[0];
    const int*   item_indexes = (const int*)  d_in[1];
    const int*   sample_ids   = (const int*)  d_in[2];
    const int*   roots        = (const int*)  d_in[3];
    const float* user_infos   = (const float*)d_in[4];
    const float* item_infos   = (const float*)d_in[5];
    const float* adj_matrix   = (const float*)d_in[6];
    const float* uid_emb      = (const float*)d_in[7];
    const float* sid_emb      = (const float*)d_in[8];
    const float* Wu           = (const float*)d_in[9];
    const float* bu           = (const float*)d_in[10];
    const float* Wi           = (const float*)d_in[11];
    const float* bi           = (const float*)d_in[12];
    const float* W1           = (const float*)d_in[13];
    const float* b1           = (const float*)d_in[14];
    const float* W2           = (const float*)d_in[15];
    const float* b2           = (const float*)d_in[16];
    const float* mW0          = (const float*)d_in[17];
    const float* mb0          = (const float*)d_in[18];
    const float* mW1          = (const float*)d_in[19];
    const float* mb1          = (const float*)d_in[20];
    const float* mW2          = (const float*)d_in[21];
    const float* mb2          = (const float*)d_in[22];
    float* out = (float*)d_out;

    adjx_kernel<<<NN, DD>>>(user_infos, item_infos, Wu, bu, Wi, bi);
    ax1_kernel<<<(NN + 15) / 16, 256>>>(W1);
    mix_kernel<<<BB / 2, 256>>>(sample_ids, roots, adj_matrix, b1);
    tail_kernel<<<BB / 16, 256>>>(user_indexes, item_indexes, uid_emb, sid_emb,
                                  W2, b2, mW0, mb0, mW1, mb1, mW2, mb2,
                                  out);
}

// round 12
// speedup vs baseline: 5.7572x; 1.0111x over previous
#include <cuda_runtime.h>
#include <cuda_bf16.h>

#define NU 339
#define NI 5825
#define NN 6164          // NU + NI
#define BB 32768
#define SS 20
#define DD 128
#define FF 8

// Scratch (device globals: allocation-free per harness rules)
__device__ float g_adjx[NN * DD];                  // 3.2 MB
__device__ float g_AX1[NN * 2 * DD];               // 6.3 MB (L2-resident)
__device__ float g_t2[(size_t)BB * 2 * 256];       // 67 MB

// ---------------------------------------------------------------------------
// Kernel A: adj_x = l2norm(user_infos@Wu + bu) ++ l2norm(item_infos@Wi + bi)
// ---------------------------------------------------------------------------
__global__ __launch_bounds__(DD) void adjx_kernel(
    const float* __restrict__ user_infos, const float* __restrict__ item_infos,
    const float* __restrict__ Wu, const float* __restrict__ bu,
    const float* __restrict__ Wi, const float* __restrict__ bi)
{
    int r = blockIdx.x;
    int d = threadIdx.x;
    const float* feat;
    const float* W;
    const float* bv;
    if (r < NU) { feat = user_infos + r * FF;        W = Wu; bv = bu; }
    else        { feat = item_infos + (r - NU) * FF; W = Wi; bv = bi; }

    float acc = bv[d];
#pragma unroll
    for (int f = 0; f < FF; f++) acc = fmaf(feat[f], W[f * DD + d], acc);

    __shared__ float red[4];
    float sq = acc * acc;
#pragma unroll
    for (int o = 16; o > 0; o >>= 1) sq += __shfl_xor_sync(0xffffffffu, sq, o);
    if ((threadIdx.x & 31) == 0) red[threadIdx.x >> 5] = sq;
    __syncthreads();
    float tot = red[0] + red[1] + red[2] + red[3];
    float nrm = fmaxf(sqrtf(tot), 1e-12f);
    g_adjx[r * DD + d] = acc / nrm;
}

// ---------------------------------------------------------------------------
// Kernel B: AX1 = adjx @ W1   (NN x 256, K=128).  NO bias (b1 added in mix).
// ---------------------------------------------------------------------------
__global__ __launch_bounds__(256) void ax1_kernel(const float* __restrict__ W1)
{
    __shared__ float sx[16][128];
    const int tid = threadIdx.x;
    const int r0 = blockIdx.x * 16;

    for (int id = tid; id < 512; id += 256) {
        int r = id >> 5, q = id & 31;
        float4 v = (r0 + r < NN)
            ? *(const float4*)&g_adjx[(long)(r0 + r) * DD + q * 4]
            : make_float4(0.f, 0.f, 0.f, 0.f);
        *(float4*)&sx[r][q * 4] = v;
    }
    __syncthreads();

    float acc[16];
#pragma unroll
    for (int i = 0; i < 16; i++) acc[i] = 0.f;

    for (int k = 0; k < DD; k++) {
        float w = __ldg(&W1[(long)k * 256 + tid]);
#pragma unroll
        for (int i = 0; i < 16; i++) acc[i] = fmaf(sx[i][k], w, acc[i]);
    }

#pragma unroll
    for (int i = 0; i < 16; i++)
        if (r0 + i < NN) g_AX1[(long)(r0 + i) * 256 + tid] = acc[i];
}

// ---------------------------------------------------------------------------
// Kernel C: mix. 2 elements per block, 128 threads/element, thread owns 2
// contiguous columns. Independent accumulators hacc[20] (no serial chains);
// AX1 row streamed per-j (double-buffered LDG); adj columns read as packed
// float4 from transposed smem tile.
//   h1[i][c] = relu(b1[c] + sum_j sub_adj[i][j] * AX1[sid[j]][c])
//   t2[r][c] = sum_i sub_adj[root_r][i] * h1[i][c]
// ---------------------------------------------------------------------------
__global__ __launch_bounds__(256) void mix_kernel(
    const int* __restrict__ sample_ids,
    const int* __restrict__ roots,
    const float* __restrict__ adj,
    const float* __restrict__ b1)
{
    __shared__ int   s_sid[2][SS];
    __shared__ float s_adjT[2][SS][24];   // s_adjT[e][j][i] = sub_adj[i][j]
    __shared__ int   s_rt[2][2];

    const int tid = threadIdx.x;
    const int e = tid >> 7, l = tid & 127;
    const int b0 = blockIdx.x * 2;

    if (tid < 2 * SS) s_sid[tid / SS][tid % SS] = sample_ids[b0 * SS + tid];
    if (tid < 4) s_rt[tid >> 1][tid & 1] = roots[b0 * 2 + tid];
    __syncthreads();

    for (int id = tid; id < 2 * SS * SS; id += 256) {
        int ee = id / 400, rem = id % 400, jj = rem / SS, ii = rem % SS;
        s_adjT[ee][jj][ii] =
            __ldg(&adj[(long)s_sid[ee][ii] * NN + s_sid[ee][jj]]);
    }
    __syncthreads();

    const float2 bc = __ldg((const float2*)&b1[l * 2]);

    float2 hacc[SS];
#pragma unroll
    for (int i = 0; i < SS; i++) hacc[i] = bc;

    // software-pipelined AX1 streaming: 20 j-iterations, 40 indep FMAs each
    float2 axj = __ldg((const float2*)&g_AX1[(long)s_sid[e][0] * 256 + l * 2]);
#pragma unroll
    for (int j = 0; j < SS; j++) {
        float2 axn;
        if (j + 1 < SS)
            axn = __ldg((const float2*)&g_AX1[(long)s_sid[e][j + 1] * 256 + l * 2]);
        float4 a0 = *(const float4*)&s_adjT[e][j][0];
        float4 a1 = *(const float4*)&s_adjT[e][j][4];
        float4 a2 = *(const float4*)&s_adjT[e][j][8];
        float4 a3 = *(const float4*)&s_adjT[e][j][12];
        float4 a4 = *(const float4*)&s_adjT[e][j][16];
        const float* av = (const float*)&a0;   // a0..a4 contiguous? no — use per-vec
        hacc[0].x  = fmaf(a0.x, axj.x, hacc[0].x);  hacc[0].y  = fmaf(a0.x, axj.y, hacc[0].y);
        hacc[1].x  = fmaf(a0.y, axj.x, hacc[1].x);  hacc[1].y  = fmaf(a0.y, axj.y, hacc[1].y);
        hacc[2].x  = fmaf(a0.z, axj.x, hacc[2].x);  hacc[2].y  = fmaf(a0.z, axj.y, hacc[2].y);
        hacc[3].x  = fmaf(a0.w, axj.x, hacc[3].x);  hacc[3].y  = fmaf(a0.w, axj.y, hacc[3].y);
        hacc[4].x  = fmaf(a1.x, axj.x, hacc[4].x);  hacc[4].y  = fmaf(a1.x, axj.y, hacc[4].y);
        hacc[5].x  = fmaf(a1.y, axj.x, hacc[5].x);  hacc[5].y  = fmaf(a1.y, axj.y, hacc[5].y);
        hacc[6].x  = fmaf(a1.z, axj.x, hacc[6].x);  hacc[6].y  = fmaf(a1.z, axj.y, hacc[6].y);
        hacc[7].x  = fmaf(a1.w, axj.x, hacc[7].x);  hacc[7].y  = fmaf(a1.w, axj.y, hacc[7].y);
        hacc[8].x  = fmaf(a2.x, axj.x, hacc[8].x);  hacc[8].y  = fmaf(a2.x, axj.y, hacc[8].y);
        hacc[9].x  = fmaf(a2.y, axj.x, hacc[9].x);  hacc[9].y  = fmaf(a2.y, axj.y, hacc[9].y);
        hacc[10].x = fmaf(a2.z, axj.x, hacc[10].x); hacc[10].y = fmaf(a2.z, axj.y, hacc[10].y);
        hacc[11].x = fmaf(a2.w, axj.x, hacc[11].x); hacc[11].y = fmaf(a2.w, axj.y, hacc[11].y);
        hacc[12].x = fmaf(a3.x, axj.x, hacc[12].x); hacc[12].y = fmaf(a3.x, axj.y, hacc[12].y);
        hacc[13].x = fmaf(a3.y, axj.x, hacc[13].x); hacc[13].y = fmaf(a3.y, axj.y, hacc[13].y);
        hacc[14].x = fmaf(a3.z, axj.x, hacc[14].x); hacc[14].y = fmaf(a3.z, axj.y, hacc[14].y);
        hacc[15].x = fmaf(a3.w, axj.x, hacc[15].x); hacc[15].y = fmaf(a3.w, axj.y, hacc[15].y);
        hacc[16].x = fmaf(a4.x, axj.x, hacc[16].x); hacc[16].y = fmaf(a4.x, axj.y, hacc[16].y);
        hacc[17].x = fmaf(a4.y, axj.x, hacc[17].x); hacc[17].y = fmaf(a4.y, axj.y, hacc[17].y);
        hacc[18].x = fmaf(a4.z, axj.x, hacc[18].x); hacc[18].y = fmaf(a4.z, axj.y, hacc[18].y);
        hacc[19].x = fmaf(a4.w, axj.x, hacc[19].x); hacc[19].y = fmaf(a4.w, axj.y, hacc[19].y);
        (void)av;
        axj = axn;
    }

    const int r0 = s_rt[e][0], r1 = s_rt[e][1];
    float2 t0 = make_float2(0.f, 0.f);
    float2 t1 = make_float2(0.f, 0.f);
#pragma unroll
    for (int i = 0; i < SS; i++) {
        float hx = fmaxf(hacc[i].x, 0.f);
        float hy = fmaxf(hacc[i].y, 0.f);
        float w0 = s_adjT[e][i][r0];     // = sub_adj[root0][i]
        float w1 = s_adjT[e][i][r1];
        t0.x = fmaf(w0, hx, t0.x); t0.y = fmaf(w0, hy, t0.y);
        t1.x = fmaf(w1, hx, t1.x); t1.y = fmaf(w1, hy, t1.y);
    }

    const long base = (long)(b0 + e) * 512;
    *(float2*)&g_t2[base + l * 2]       = t0;
    *(float2*)&g_t2[base + 256 + l * 2] = t1;
}

// ---------------------------------------------------------------------------
// Kernel D: tail, 32 elements per block, 256 threads, 80KB dynamic smem.
// grid = BB/32.
// dsm layout (floats): [0:16384) t2 (64 rows x 256); after ft, x overwrites
//   [0:8192) (32x256), y1 at [8192:12288) (32x128), y2 at [12288:14336);
//   wB = [16384:20480) weight chunks.
// ft microtile: 8 rows x 4 cols per thread (weight bytes amortized over 8 rows).
// ---------------------------------------------------------------------------
__global__ __launch_bounds__(256) void tail_kernel(
    const int*   __restrict__ user_idx,
    const int*   __restrict__ item_idx,
    const float* __restrict__ uid_emb,
    const float* __restrict__ sid_emb,
    const float* __restrict__ W2, const float* __restrict__ b2,
    const float* __restrict__ mW0, const float* __restrict__ mb0,
    const float* __restrict__ mW1, const float* __restrict__ mb1,
    const float* __restrict__ mW2, const float* __restrict__ mb2,
    float* __restrict__ out)
{
    extern __shared__ float dsm[];
    float* bufA = dsm;            // 16384 floats
    float* wB   = dsm + 16384;    // 4096 floats

    const int tid = threadIdx.x;
    const int tx = tid & 31, ty = tid >> 5;
    const int b0 = blockIdx.x * 32;

    // load t2 for 32 elements (16384 floats, contiguous)
    {
        const float4* src = (const float4*)(g_t2 + (long)b0 * 512);
        for (int id = tid; id < 4096; id += 256) ((float4*)bufA)[id] = src[id];
    }
    __syncthreads();

    // ---- ft = t2 @ W2: 64 rows (er = ty+8s, s<8) x 128 cols, K=256 ----
    float f[8][4];
#pragma unroll
    for (int s = 0; s < 8; s++)
#pragma unroll
        for (int c = 0; c < 4; c++) f[s][c] = 0.f;

    for (int c0 = 0; c0 < 256; c0 += 32) {
        for (int id = tid; id < 1024; id += 256) {
            int k = id >> 5, dq = id & 31;
            *(float4*)&wB[k * 128 + dq * 4] =
                *(const float4*)&W2[(long)(c0 + k) * 128 + dq * 4];
        }
        __syncthreads();
#pragma unroll
        for (int kk4 = 0; kk4 < 8; kk4++) {
            float4 tv[8];
#pragma unroll
            for (int s = 0; s < 8; s++)
                tv[s] = *(const float4*)&bufA[(ty + 8 * s) * 256 + c0 + kk4 * 4];
#pragma unroll
            for (int u = 0; u < 4; u++) {
                float4 w4 = *(const float4*)&wB[(kk4 * 4 + u) * 128 + tx * 4];
#pragma unroll
                for (int s = 0; s < 8; s++) {
                    float t = ((const float*)&tv[s])[u];
                    f[s][0] = fmaf(t, w4.x, f[s][0]);
                    f[s][1] = fmaf(t, w4.y, f[s][1]);
                    f[s][2] = fmaf(t, w4.z, f[s][2]);
                    f[s][3] = fmaf(t, w4.w, f[s][3]);
                }
            }
        }
        __syncthreads();
    }

    // ---- merge with id_vec: x[e][r*128+d] = 0.6*emb + 0.4*relu(f + b2) ----
    {
        float4 bv = *(const float4*)&b2[tx * 4];
#pragma unroll
        for (int s = 0; s < 8; s++) {
            int er = ty + 8 * s;
            int e = er >> 1, r = er & 1;
            const float* emb = (r == 0)
                ? &uid_emb[(long)__ldg(&user_idx[b0 + e]) * DD]
                : &sid_emb[(long)__ldg(&item_idx[b0 + e]) * DD];
            float4 idv = __ldg((const float4*)&emb[tx * 4]);
            f[s][0] = 0.6f * idv.x + 0.4f * fmaxf(f[s][0] + bv.x, 0.f);
            f[s][1] = 0.6f * idv.y + 0.4f * fmaxf(f[s][1] + bv.y, 0.f);
            f[s][2] = 0.6f * idv.z + 0.4f * fmaxf(f[s][2] + bv.z, 0.f);
            f[s][3] = 0.6f * idv.w + 0.4f * fmaxf(f[s][3] + bv.w, 0.f);
        }
    }
    __syncthreads();   // all t2 reads done; safe to overwrite bufA[0:8192)
#pragma unroll
    for (int s = 0; s < 8; s++) {
        int er = ty + 8 * s;
        int e = er >> 1, r = er & 1;
        *(float4*)&bufA[e * 256 + r * 128 + tx * 4] = *(float4*)&f[s][0];
    }
    __syncthreads();

    // ---- MLP0: y1 = relu(x @ mW0 + mb0): elems e = ty+8s (s<4), cols tx*4 ----
    float g0[4][4];
#pragma unroll
    for (int s = 0; s < 4; s++)
#pragma unroll
        for (int c = 0; c < 4; c++) g0[s][c] = 0.f;

    for (int c0 = 0; c0 < 256; c0 += 32) {
        for (int id = tid; id < 1024; id += 256) {
            int k = id >> 5, dq = id & 31;
            *(float4*)&wB[k * 128 + dq * 4] =
                *(const float4*)&mW0[(long)(c0 + k) * 128 + dq * 4];
        }
        __syncthreads();
#pragma unroll
        for (int kk4 = 0; kk4 < 8; kk4++) {
            float4 xv[4];
#pragma unroll
            for (int s = 0; s < 4; s++)
                xv[s] = *(const float4*)&bufA[(ty + 8 * s) * 256 + c0 + kk4 * 4];
#pragma unroll
            for (int u = 0; u < 4; u++) {
                float4 w4 = *(const float4*)&wB[(kk4 * 4 + u) * 128 + tx * 4];
#pragma unroll
                for (int s = 0; s < 4; s++) {
                    float x = ((const float*)&xv[s])[u];
                    g0[s][0] = fmaf(x, w4.x, g0[s][0]);
                    g0[s][1] = fmaf(x, w4.y, g0[s][1]);
                    g0[s][2] = fmaf(x, w4.z, g0[s][2]);
                    g0[s][3] = fmaf(x, w4.w, g0[s][3]);
                }
            }
        }
        __syncthreads();
    }
    {
        float4 bv = __ldg((const float4*)&mb0[tx * 4]);
#pragma unroll
        for (int s = 0; s < 4; s++) {
            int e = ty + 8 * s;
            float4 y;
            y.x = fmaxf(g0[s][0] + bv.x, 0.f); y.y = fmaxf(g0[s][1] + bv.y, 0.f);
            y.z = fmaxf(g0[s][2] + bv.z, 0.f); y.w = fmaxf(g0[s][3] + bv.w, 0.f);
            *(float4*)&bufA[8192 + e * 128 + tx * 4] = y;   // y1[e][128]
        }
    }
    __syncthreads();

    // ---- MLP1: y2 = relu(y1 @ mW1 + mb1): elems e = ty+8s (s<4), cols tx*2 ----
    {
        const int oo = tx * 2;
        float a[4][2];
#pragma unroll
        for (int s = 0; s < 4; s++) { a[s][0] = 0.f; a[s][1] = 0.f; }
        for (int c0 = 0; c0 < 128; c0 += 64) {
            for (int id = tid; id < 1024; id += 256) {
                int k = id >> 4, dq = id & 15;
                *(float4*)&wB[k * 64 + dq * 4] =
                    *(const float4*)&mW1[(long)(c0 + k) * 64 + dq * 4];
            }
            __syncthreads();
#pragma unroll
            for (int kk4 = 0; kk4 < 16; kk4++) {
                float4 yv[4];
#pragma unroll
                for (int s = 0; s < 4; s++)
                    yv[s] = *(const float4*)&bufA[8192 + (ty + 8 * s) * 128 + c0 + kk4 * 4];
#pragma unroll
                for (int u = 0; u < 4; u++) {
                    float2 w2 = *(const float2*)&wB[(kk4 * 4 + u) * 64 + oo];
#pragma unroll
                    for (int s = 0; s < 4; s++) {
                        float y = ((const float*)&yv[s])[u];
                        a[s][0] = fmaf(y, w2.x, a[s][0]);
                        a[s][1] = fmaf(y, w2.y, a[s][1]);
                    }
                }
            }
            __syncthreads();
        }
        float2 bv = __ldg((const float2*)&mb1[oo]);
#pragma unroll
        for (int s = 0; s < 4; s++) {
            int e = ty + 8 * s;
            bufA[12288 + e * 64 + oo]     = fmaxf(a[s][0] + bv.x, 0.f);
            bufA[12288 + e * 64 + oo + 1] = fmaxf(a[s][1] + bv.y, 0.f);
        }
    }
    __syncthreads();

    // ---- MLP2: warp ty handles elements ty+8s (s<4) ----
    {
        float wlo = __ldg(&mW2[tx]);
        float whi = __ldg(&mW2[32 + tx]);
        float bias = __ldg(&mb2[0]);
#pragma unroll
        for (int s = 0; s < 4; s++) {
            int e = ty + 8 * s;
            float p = bufA[12288 + e * 64 + tx] * wlo +
                      bufA[12288 + e * 64 + 32 + tx] * whi;
#pragma unroll
            for (int o = 16; o > 0; o >>= 1)
                p += __shfl_xor_sync(0xffffffffu, p, o);
            if (tx == 0) out[b0 + e] = fmaxf(p + bias, 0.f);
        }
    }
}

// ---------------------------------------------------------------------------
extern "C" void kernel_launch(void* const* d_in, const int* in_sizes, int n_in,
                              void* d_out, int out_size)
{
    const int*   user_indexes = (const int*)  d_in[0];
    const int*   item_indexes = (const int*)  d_in[1];
    const int*   sample_ids   = (const int*)  d_in[2];
    const int*   roots        = (const int*)  d_in[3];
    const float* user_infos   = (const float*)d_in[4];
    const float* item_infos   = (const float*)d_in[5];
    const float* adj_matrix   = (const float*)d_in[6];
    const float* uid_emb      = (const float*)d_in[7];
    const float* sid_emb      = (const float*)d_in[8];
    const float* Wu           = (const float*)d_in[9];
    const float* bu           = (const float*)d_in[10];
    const float* Wi           = (const float*)d_in[11];
    const float* bi           = (const float*)d_in[12];
    const float* W1           = (const float*)d_in[13];
    const float* b1           = (const float*)d_in[14];
    const float* W2           = (const float*)d_in[15];
    const float* b2           = (const float*)d_in[16];
    const float* mW0          = (const float*)d_in[17];
    const float* mb0          = (const float*)d_in[18];
    const float* mW1          = (const float*)d_in[19];
    const float* mb1          = (const float*)d_in[20];
    const float* mW2          = (const float*)d_in[21];
    const float* mb2          = (const float*)d_in[22];
    float* out = (float*)d_out;

    const int TAIL_SMEM = 20480 * sizeof(float);   // 80 KB
    cudaFuncSetAttribute(tail_kernel,
                         cudaFuncAttributeMaxDynamicSharedMemorySize, TAIL_SMEM);

    adjx_kernel<<<NN, DD>>>(user_infos, item_infos, Wu, bu, Wi, bi);
    ax1_kernel<<<(NN + 15) / 16, 256>>>(W1);
    mix_kernel<<<BB / 2, 256>>>(sample_ids, roots, adj_matrix, b1);
    tail_kernel<<<BB / 32, 256, TAIL_SMEM>>>(user_indexes, item_indexes,
                                             uid_emb, sid_emb,
                                             W2, b2, mW0, mb0, mW1, mb1,
                                             mW2, mb2, out);
}

// round 13
// speedup vs baseline: 5.9110x; 1.0267x over previous
#include <cuda_runtime.h>
#include <cuda_bf16.h>

#define NU 339
#define NI 5825
#define NN 6164          // NU + NI
#define BB 32768
#define SS 20
#define DD 128
#define FF 8

// Scratch (device globals: allocation-free per harness rules)
__device__ float g_adjx[NN * DD];                  // 3.2 MB
__device__ float g_AX1[NN * 2 * DD];               // 6.3 MB (L2-resident)
__device__ float g_t2[(size_t)BB * 2 * 256];       // 67 MB

// ---- packed f32x2 helpers (Blackwell FFMA2; exact per-lane fma.rn) --------
__device__ __forceinline__ unsigned long long pk2(float x, float y) {
    unsigned long long r;
    asm("mov.b64 %0, {%1, %2};" : "=l"(r) : "f"(x), "f"(y));
    return r;
}
__device__ __forceinline__ float2 upk2(unsigned long long v) {
    float2 f;
    asm("mov.b64 {%0, %1}, %2;" : "=f"(f.x), "=f"(f.y) : "l"(v));
    return f;
}
__device__ __forceinline__ unsigned long long fma2_(unsigned long long a,
    unsigned long long b, unsigned long long c) {
    unsigned long long d;
    asm("fma.rn.f32x2 %0, %1, %2, %3;" : "=l"(d) : "l"(a), "l"(b), "l"(c));
    return d;
}

// ---------------------------------------------------------------------------
// Kernel A: adj_x = l2norm(user_infos@Wu + bu) ++ l2norm(item_infos@Wi + bi)
// ---------------------------------------------------------------------------
__global__ __launch_bounds__(DD) void adjx_kernel(
    const float* __restrict__ user_infos, const float* __restrict__ item_infos,
    const float* __restrict__ Wu, const float* __restrict__ bu,
    const float* __restrict__ Wi, const float* __restrict__ bi)
{
    int r = blockIdx.x;
    int d = threadIdx.x;
    const float* feat;
    const float* W;
    const float* bv;
    if (r < NU) { feat = user_infos + r * FF;        W = Wu; bv = bu; }
    else        { feat = item_infos + (r - NU) * FF; W = Wi; bv = bi; }

    float acc = bv[d];
#pragma unroll
    for (int f = 0; f < FF; f++) acc = fmaf(feat[f], W[f * DD + d], acc);

    __shared__ float red[4];
    float sq = acc * acc;
#pragma unroll
    for (int o = 16; o > 0; o >>= 1) sq += __shfl_xor_sync(0xffffffffu, sq, o);
    if ((threadIdx.x & 31) == 0) red[threadIdx.x >> 5] = sq;
    __syncthreads();
    float tot = red[0] + red[1] + red[2] + red[3];
    float nrm = fmaxf(sqrtf(tot), 1e-12f);
    g_adjx[r * DD + d] = acc / nrm;
}

// ---------------------------------------------------------------------------
// Kernel B: AX1 = adjx @ W1   (NN x 256, K=128).  NO bias (b1 added in mix).
// ---------------------------------------------------------------------------
__global__ __launch_bounds__(256) void ax1_kernel(const float* __restrict__ W1)
{
    __shared__ float sx[16][128];
    const int tid = threadIdx.x;
    const int r0 = blockIdx.x * 16;

    for (int id = tid; id < 512; id += 256) {
        int r = id >> 5, q = id & 31;
        float4 v = (r0 + r < NN)
            ? *(const float4*)&g_adjx[(long)(r0 + r) * DD + q * 4]
            : make_float4(0.f, 0.f, 0.f, 0.f);
        *(float4*)&sx[r][q * 4] = v;
    }
    __syncthreads();

    float acc[16];
#pragma unroll
    for (int i = 0; i < 16; i++) acc[i] = 0.f;

    for (int k = 0; k < DD; k++) {
        float w = __ldg(&W1[(long)k * 256 + tid]);
#pragma unroll
        for (int i = 0; i < 16; i++) acc[i] = fmaf(sx[i][k], w, acc[i]);
    }

#pragma unroll
    for (int i = 0; i < 16; i++)
        if (r0 + i < NN) g_AX1[(long)(r0 + i) * 256 + tid] = acc[i];
}

// ---------------------------------------------------------------------------
// Kernel C: mix. 2 elements per block, 128 threads/element, thread owns 2
// contiguous columns. Accumulators packed f32x2 across row pairs (i,i+1);
// adj pairs pre-packed in smem (ulonglong2 loads); AX1 streamed per-j.
//   h1[i][c] = relu(b1[c] + sum_j sub_adj[i][j] * AX1[sid[j]][c])
//   t2[r][c] = sum_i sub_adj[root_r][i] * h1[i][c]
// ---------------------------------------------------------------------------
__global__ __launch_bounds__(256) void mix_kernel(
    const int* __restrict__ sample_ids,
    const int* __restrict__ roots,
    const float* __restrict__ adj,
    const float* __restrict__ b1)
{
    __shared__ int   s_sid[2][SS];
    __shared__ float s_adjT[2][SS][24];   // s_adjT[e][j][i] = sub_adj[i][j]
    __shared__ int   s_rt[2][2];

    const int tid = threadIdx.x;
    const int e = tid >> 7, l = tid & 127;
    const int b0 = blockIdx.x * 2;

    if (tid < 2 * SS) s_sid[tid / SS][tid % SS] = sample_ids[b0 * SS + tid];
    if (tid < 4) s_rt[tid >> 1][tid & 1] = roots[b0 * 2 + tid];
    __syncthreads();

    for (int id = tid; id < 2 * SS * SS; id += 256) {
        int ee = id / 400, rem = id % 400, jj = rem / SS, ii = rem % SS;
        s_adjT[ee][jj][ii] =
            __ldg(&adj[(long)s_sid[ee][ii] * NN + s_sid[ee][jj]]);
    }
    __syncthreads();

    const float2 bc = __ldg((const float2*)&b1[l * 2]);

    // H0[p] = (h[2p],h[2p+1]) for column 0; H1 for column 1
    unsigned long long H0[10], H1[10];
    {
        unsigned long long b0p = pk2(bc.x, bc.x);
        unsigned long long b1p = pk2(bc.y, bc.y);
#pragma unroll
        for (int p = 0; p < 10; p++) { H0[p] = b0p; H1[p] = b1p; }
    }

    float2 axj = __ldg((const float2*)&g_AX1[(long)s_sid[e][0] * 256 + l * 2]);
#pragma unroll
    for (int j = 0; j < SS; j++) {
        float2 axn;
        if (j + 1 < SS)
            axn = __ldg((const float2*)&g_AX1[(long)s_sid[e][j + 1] * 256 + l * 2]);
        // adj row pairs, pre-packed: (a[0],a[1]),(a[2],a[3]),... 16B-aligned
        ulonglong2 A0 = *(const ulonglong2*)&s_adjT[e][j][0];
        ulonglong2 A1 = *(const ulonglong2*)&s_adjT[e][j][4];
        ulonglong2 A2 = *(const ulonglong2*)&s_adjT[e][j][8];
        ulonglong2 A3 = *(const ulonglong2*)&s_adjT[e][j][12];
        ulonglong2 A4 = *(const ulonglong2*)&s_adjT[e][j][16];
        unsigned long long ax0 = pk2(axj.x, axj.x);
        unsigned long long ax1v = pk2(axj.y, axj.y);
        H0[0] = fma2_(A0.x, ax0, H0[0]);  H1[0] = fma2_(A0.x, ax1v, H1[0]);
        H0[1] = fma2_(A0.y, ax0, H0[1]);  H1[1] = fma2_(A0.y, ax1v, H1[1]);
        H0[2] = fma2_(A1.x, ax0, H0[2]);  H1[2] = fma2_(A1.x, ax1v, H1[2]);
        H0[3] = fma2_(A1.y, ax0, H0[3]);  H1[3] = fma2_(A1.y, ax1v, H1[3]);
        H0[4] = fma2_(A2.x, ax0, H0[4]);  H1[4] = fma2_(A2.x, ax1v, H1[4]);
        H0[5] = fma2_(A2.y, ax0, H0[5]);  H1[5] = fma2_(A2.y, ax1v, H1[5]);
        H0[6] = fma2_(A3.x, ax0, H0[6]);  H1[6] = fma2_(A3.x, ax1v, H1[6]);
        H0[7] = fma2_(A3.y, ax0, H0[7]);  H1[7] = fma2_(A3.y, ax1v, H1[7]);
        H0[8] = fma2_(A4.x, ax0, H0[8]);  H1[8] = fma2_(A4.x, ax1v, H1[8]);
        H0[9] = fma2_(A4.y, ax0, H0[9]);  H1[9] = fma2_(A4.y, ax1v, H1[9]);
        axj = axn;
    }

    const int r0 = s_rt[e][0], r1 = s_rt[e][1];
    float2 t0 = make_float2(0.f, 0.f);
    float2 t1 = make_float2(0.f, 0.f);
#pragma unroll
    for (int p = 0; p < 10; p++) {
        float2 ha = upk2(H0[p]);   // col0: rows 2p, 2p+1
        float2 hb = upk2(H1[p]);   // col1: rows 2p, 2p+1
        float h0a = fmaxf(ha.x, 0.f), h0b = fmaxf(ha.y, 0.f);
        float h1a = fmaxf(hb.x, 0.f), h1b = fmaxf(hb.y, 0.f);
        float wa0 = s_adjT[e][2 * p][r0],     wb0 = s_adjT[e][2 * p + 1][r0];
        float wa1 = s_adjT[e][2 * p][r1],     wb1 = s_adjT[e][2 * p + 1][r1];
        t0.x = fmaf(wa0, h0a, t0.x); t0.x = fmaf(wb0, h0b, t0.x);
        t0.y = fmaf(wa0, h1a, t0.y); t0.y = fmaf(wb0, h1b, t0.y);
        t1.x = fmaf(wa1, h0a, t1.x); t1.x = fmaf(wb1, h0b, t1.x);
        t1.y = fmaf(wa1, h1a, t1.y); t1.y = fmaf(wb1, h1b, t1.y);
    }

    const long base = (long)(b0 + e) * 512;
    *(float2*)&g_t2[base + l * 2]       = t0;
    *(float2*)&g_t2[base + 256 + l * 2] = t1;
}

// ---------------------------------------------------------------------------
// Kernel D: tail, 32 elements per block, 256 threads, 80KB dynamic smem.
// f32x2-packed microkernels (weights pre-packed via ulonglong2 smem loads).
// dsm layout (floats): [0:16384) t2 (64x256) -> x[0:8192), y1[8192:12288),
//   y2[12288:14336); wB = [16384:20480).
// ---------------------------------------------------------------------------
__global__ __launch_bounds__(256) void tail_kernel(
    const int*   __restrict__ user_idx,
    const int*   __restrict__ item_idx,
    const float* __restrict__ uid_emb,
    const float* __restrict__ sid_emb,
    const float* __restrict__ W2, const float* __restrict__ b2,
    const float* __restrict__ mW0, const float* __restrict__ mb0,
    const float* __restrict__ mW1, const float* __restrict__ mb1,
    const float* __restrict__ mW2, const float* __restrict__ mb2,
    float* __restrict__ out)
{
    extern __shared__ float dsm[];
    float* bufA = dsm;            // 16384 floats
    float* wB   = dsm + 16384;    // 4096 floats

    const int tid = threadIdx.x;
    const int tx = tid & 31, ty = tid >> 5;
    const int b0 = blockIdx.x * 32;

    // load t2 for 32 elements (16384 floats, contiguous)
    {
        const float4* src = (const float4*)(g_t2 + (long)b0 * 512);
        for (int id = tid; id < 4096; id += 256) ((float4*)bufA)[id] = src[id];
    }
    __syncthreads();

    // ---- ft = t2 @ W2: 64 rows (er = ty+8s, s<8) x 128 cols, K=256 ----
    unsigned long long f2[8][2];
#pragma unroll
    for (int s = 0; s < 8; s++) { f2[s][0] = 0ULL; f2[s][1] = 0ULL; }

    for (int c0 = 0; c0 < 256; c0 += 32) {
        for (int id = tid; id < 1024; id += 256) {
            int k = id >> 5, dq = id & 31;
            *(float4*)&wB[k * 128 + dq * 4] =
                *(const float4*)&W2[(long)(c0 + k) * 128 + dq * 4];
        }
        __syncthreads();
#pragma unroll
        for (int kk4 = 0; kk4 < 8; kk4++) {
            float4 tv[8];
#pragma unroll
            for (int s = 0; s < 8; s++)
                tv[s] = *(const float4*)&bufA[(ty + 8 * s) * 256 + c0 + kk4 * 4];
#pragma unroll
            for (int u = 0; u < 4; u++) {
                ulonglong2 wp = *(const ulonglong2*)&wB[(kk4 * 4 + u) * 128 + tx * 4];
#pragma unroll
                for (int s = 0; s < 8; s++) {
                    float t = ((const float*)&tv[s])[u];
                    unsigned long long tb = pk2(t, t);
                    f2[s][0] = fma2_(tb, wp.x, f2[s][0]);
                    f2[s][1] = fma2_(tb, wp.y, f2[s][1]);
                }
            }
        }
        __syncthreads();
    }

    // unpack + merge with id_vec: x[e][r*128+d] = 0.6*emb + 0.4*relu(f + b2)
    float f[8][4];
#pragma unroll
    for (int s = 0; s < 8; s++) {
        float2 p0 = upk2(f2[s][0]);
        float2 p1 = upk2(f2[s][1]);
        f[s][0] = p0.x; f[s][1] = p0.y; f[s][2] = p1.x; f[s][3] = p1.y;
    }
    {
        float4 bv = *(const float4*)&b2[tx * 4];
#pragma unroll
        for (int s = 0; s < 8; s++) {
            int er = ty + 8 * s;
            int e = er >> 1, r = er & 1;
            const float* emb = (r == 0)
                ? &uid_emb[(long)__ldg(&user_idx[b0 + e]) * DD]
                : &sid_emb[(long)__ldg(&item_idx[b0 + e]) * DD];
            float4 idv = __ldg((const float4*)&emb[tx * 4]);
            f[s][0] = 0.6f * idv.x + 0.4f * fmaxf(f[s][0] + bv.x, 0.f);
            f[s][1] = 0.6f * idv.y + 0.4f * fmaxf(f[s][1] + bv.y, 0.f);
            f[s][2] = 0.6f * idv.z + 0.4f * fmaxf(f[s][2] + bv.z, 0.f);
            f[s][3] = 0.6f * idv.w + 0.4f * fmaxf(f[s][3] + bv.w, 0.f);
        }
    }
    __syncthreads();   // all t2 reads done; safe to overwrite bufA[0:8192)
#pragma unroll
    for (int s = 0; s < 8; s++) {
        int er = ty + 8 * s;
        int e = er >> 1, r = er & 1;
        *(float4*)&bufA[e * 256 + r * 128 + tx * 4] = *(float4*)&f[s][0];
    }
    __syncthreads();

    // ---- MLP0: y1 = relu(x @ mW0 + mb0): elems e = ty+8s (s<4), cols tx*4 ----
    unsigned long long g2[4][2];
#pragma unroll
    for (int s = 0; s < 4; s++) { g2[s][0] = 0ULL; g2[s][1] = 0ULL; }

    for (int c0 = 0; c0 < 256; c0 += 32) {
        for (int id = tid; id < 1024; id += 256) {
            int k = id >> 5, dq = id & 31;
            *(float4*)&wB[k * 128 + dq * 4] =
                *(const float4*)&mW0[(long)(c0 + k) * 128 + dq * 4];
        }
        __syncthreads();
#pragma unroll
        for (int kk4 = 0; kk4 < 8; kk4++) {
            float4 xv[4];
#pragma unroll
            for (int s = 0; s < 4; s++)
                xv[s] = *(const float4*)&bufA[(ty + 8 * s) * 256 + c0 + kk4 * 4];
#pragma unroll
            for (int u = 0; u < 4; u++) {
                ulonglong2 wp = *(const ulonglong2*)&wB[(kk4 * 4 + u) * 128 + tx * 4];
#pragma unroll
                for (int s = 0; s < 4; s++) {
                    float x = ((const float*)&xv[s])[u];
                    unsigned long long xb = pk2(x, x);
                    g2[s][0] = fma2_(xb, wp.x, g2[s][0]);
                    g2[s][1] = fma2_(xb, wp.y, g2[s][1]);
                }
            }
        }
        __syncthreads();
    }
    {
        float4 bv = __ldg((const float4*)&mb0[tx * 4]);
#pragma unroll
        for (int s = 0; s < 4; s++) {
            int e = ty + 8 * s;
            float2 p0 = upk2(g2[s][0]);
            float2 p1 = upk2(g2[s][1]);
            float4 y;
            y.x = fmaxf(p0.x + bv.x, 0.f); y.y = fmaxf(p0.y + bv.y, 0.f);
            y.z = fmaxf(p1.x + bv.z, 0.f); y.w = fmaxf(p1.y + bv.w, 0.f);
            *(float4*)&bufA[8192 + e * 128 + tx * 4] = y;   // y1[e][128]
        }
    }
    __syncthreads();

    // ---- MLP1: y2 = relu(y1 @ mW1 + mb1): elems e = ty+8s (s<4), cols tx*2 ----
    {
        const int oo = tx * 2;
        unsigned long long a2[4];
#pragma unroll
        for (int s = 0; s < 4; s++) a2[s] = 0ULL;
        for (int c0 = 0; c0 < 128; c0 += 64) {
            for (int id = tid; id < 1024; id += 256) {
                int k = id >> 4, dq = id & 15;
                *(float4*)&wB[k * 64 + dq * 4] =
                    *(const float4*)&mW1[(long)(c0 + k) * 64 + dq * 4];
            }
            __syncthreads();
#pragma unroll
            for (int kk4 = 0; kk4 < 16; kk4++) {
                float4 yv[4];
#pragma unroll
                for (int s = 0; s < 4; s++)
                    yv[s] = *(const float4*)&bufA[8192 + (ty + 8 * s) * 128 + c0 + kk4 * 4];
#pragma unroll
                for (int u = 0; u < 4; u++) {
                    unsigned long long wp =
                        *(const unsigned long long*)&wB[(kk4 * 4 + u) * 64 + oo];
#pragma unroll
                    for (int s = 0; s < 4; s++) {
                        float y = ((const float*)&yv[s])[u];
                        a2[s] = fma2_(pk2(y, y), wp, a2[s]);
                    }
                }
            }
            __syncthreads();
        }
        float2 bv = __ldg((const float2*)&mb1[oo]);
#pragma unroll
        for (int s = 0; s < 4; s++) {
            int e = ty + 8 * s;
            float2 av = upk2(a2[s]);
            bufA[12288 + e * 64 + oo]     = fmaxf(av.x + bv.x, 0.f);
            bufA[12288 + e * 64 + oo + 1] = fmaxf(av.y + bv.y, 0.f);
        }
    }
    __syncthreads();

    // ---- MLP2: warp ty handles elements ty+8s (s<4) ----
    {
        float wlo = __ldg(&mW2[tx]);
        float whi = __ldg(&mW2[32 + tx]);
        float bias = __ldg(&mb2[0]);
#pragma unroll
        for (int s = 0; s < 4; s++) {
            int e = ty + 8 * s;
            float p = bufA[12288 + e * 64 + tx] * wlo +
                      bufA[12288 + e * 64 + 32 + tx] * whi;
#pragma unroll
            for (int o = 16; o > 0; o >>= 1)
                p += __shfl_xor_sync(0xffffffffu, p, o);
            if (tx == 0) out[b0 + e] = fmaxf(p + bias, 0.f);
        }
    }
}

// ---------------------------------------------------------------------------
extern "C" void kernel_launch(void* const* d_in, const int* in_sizes, int n_in,
                              void* d_out, int out_size)
{
    const int*   user_indexes = (const int*)  d_in[0];
    const int*   item_indexes = (const int*)  d_in[1];
    const int*   sample_ids   = (const int*)  d_in[2];
    const int*   roots        = (const int*)  d_in[3];
    const float* user_infos   = (const float*)d_in[4];
    const float* item_infos   = (const float*)d_in[5];
    const float* adj_matrix   = (const float*)d_in[6];
    const float* uid_emb      = (const float*)d_in[7];
    const float* sid_emb      = (const float*)d_in[8];
    const float* Wu           = (const float*)d_in[9];
    const float* bu           = (const float*)d_in[10];
    const float* Wi           = (const float*)d_in[11];
    const float* bi           = (const float*)d_in[12];
    const float* W1           = (const float*)d_in[13];
    const float* b1           = (const float*)d_in[14];
    const float* W2           = (const float*)d_in[15];
    const float* b2           = (const float*)d_in[16];
    const float* mW0          = (const float*)d_in[17];
    const float* mb0          = (const float*)d_in[18];
    const float* mW1          = (const float*)d_in[19];
    const float* mb1          = (const float*)d_in[20];
    const float* mW2          = (const float*)d_in[21];
    const float* mb2          = (const float*)d_in[22];
    float* out = (float*)d_out;

    const int TAIL_SMEM = 20480 * sizeof(float);   // 80 KB
    cudaFuncSetAttribute(tail_kernel,
                         cudaFuncAttributeMaxDynamicSharedMemorySize, TAIL_SMEM);

    adjx_kernel<<<NN, DD>>>(user_infos, item_infos, Wu, bu, Wi, bi);
    ax1_kernel<<<(NN + 15) / 16, 256>>>(W1);
    mix_kernel<<<BB / 2, 256>>>(sample_ids, roots, adj_matrix, b1);
    tail_kernel<<<BB / 32, 256, TAIL_SMEM>>>(user_indexes, item_indexes,
                                             uid_emb, sid_emb,
                                             W2, b2, mW0, mb0, mW1, mb1,
                                             mW2, mb2, out);
}

// round 15
// speedup vs baseline: 6.7248x; 1.1377x over previous
#include <cuda_runtime.h>
#include <cuda_bf16.h>

#define NU 339
#define NI 5825
#define NN 6164          // NU + NI
#define BB 32768
#define SS 20
#define DD 128
#define FF 8

// Scratch (device globals: allocation-free per harness rules)
__device__ float g_adjx[NN * DD];                  // 3.2 MB
__device__ float g_AX1[NN * 2 * DD];               // 6.3 MB (L2-resident)
__device__ float g_t2[(size_t)BB * 2 * 256];       // 67 MB

// ---- packed f32x2 helpers (Blackwell FFMA2; exact per-lane fma.rn) --------
__device__ __forceinline__ unsigned long long pk2(float x, float y) {
    unsigned long long r;
    asm("mov.b64 %0, {%1, %2};" : "=l"(r) : "f"(x), "f"(y));
    return r;
}
__device__ __forceinline__ float2 upk2(unsigned long long v) {
    float2 f;
    asm("mov.b64 {%0, %1}, %2;" : "=f"(f.x), "=f"(f.y) : "l"(v));
    return f;
}
__device__ __forceinline__ unsigned long long fma2_(unsigned long long a,
    unsigned long long b, unsigned long long c) {
    unsigned long long d;
    asm("fma.rn.f32x2 %0, %1, %2, %3;" : "=l"(d) : "l"(a), "l"(b), "l"(c));
    return d;
}

// ---------------------------------------------------------------------------
// Kernel A: adj_x = l2norm(user_infos@Wu + bu) ++ l2norm(item_infos@Wi + bi)
// ---------------------------------------------------------------------------
__global__ __launch_bounds__(DD) void adjx_kernel(
    const float* __restrict__ user_infos, const float* __restrict__ item_infos,
    const float* __restrict__ Wu, const float* __restrict__ bu,
    const float* __restrict__ Wi, const float* __restrict__ bi)
{
    int r = blockIdx.x;
    int d = threadIdx.x;
    const float* feat;
    const float* W;
    const float* bv;
    if (r < NU) { feat = user_infos + r * FF;        W = Wu; bv = bu; }
    else        { feat = item_infos + (r - NU) * FF; W = Wi; bv = bi; }

    float acc = bv[d];
#pragma unroll
    for (int f = 0; f < FF; f++) acc = fmaf(feat[f], W[f * DD + d], acc);

    __shared__ float red[4];
    float sq = acc * acc;
#pragma unroll
    for (int o = 16; o > 0; o >>= 1) sq += __shfl_xor_sync(0xffffffffu, sq, o);
    if ((threadIdx.x & 31) == 0) red[threadIdx.x >> 5] = sq;
    __syncthreads();
    float tot = red[0] + red[1] + red[2] + red[3];
    float nrm = fmaxf(sqrtf(tot), 1e-12f);
    g_adjx[r * DD + d] = acc / nrm;
}

// ---------------------------------------------------------------------------
// Kernel B: AX1 = adjx @ W1   (NN x 256, K=128).  NO bias (b1 added in mix).
// ---------------------------------------------------------------------------
__global__ __launch_bounds__(256) void ax1_kernel(const float* __restrict__ W1)
{
    __shared__ float sx[16][128];
    const int tid = threadIdx.x;
    const int r0 = blockIdx.x * 16;

    for (int id = tid; id < 512; id += 256) {
        int r = id >> 5, q = id & 31;
        float4 v = (r0 + r < NN)
            ? *(const float4*)&g_adjx[(long)(r0 + r) * DD + q * 4]
            : make_float4(0.f, 0.f, 0.f, 0.f);
        *(float4*)&sx[r][q * 4] = v;
    }
    __syncthreads();

    float acc[16];
#pragma unroll
    for (int i = 0; i < 16; i++) acc[i] = 0.f;

    for (int k = 0; k < DD; k++) {
        float w = __ldg(&W1[(long)k * 256 + tid]);
#pragma unroll
        for (int i = 0; i < 16; i++) acc[i] = fmaf(sx[i][k], w, acc[i]);
    }

#pragma unroll
    for (int i = 0; i < 16; i++)
        if (r0 + i < NN) g_AX1[(long)(r0 + i) * 256 + tid] = acc[i];
}

// ---------------------------------------------------------------------------
// Kernel C: mix. 2 elements per block, 128 threads/element, thread owns 2
// contiguous columns. FULL AX1 prefetch (ax[20] float2, MLP=20), then a pure
// unrolled FFMA2 block on packed row-pair accumulators.
//   h1[i][c] = relu(b1[c] + sum_j sub_adj[i][j] * AX1[sid[j]][c])
//   t2[r][c] = sum_i sub_adj[root_r][i] * h1[i][c]
// ---------------------------------------------------------------------------
__global__ __launch_bounds__(256) void mix_kernel(
    const int* __restrict__ sample_ids,
    const int* __restrict__ roots,
    const float* __restrict__ adj,
    const float* __restrict__ b1)
{
    __shared__ int   s_sid[2][SS];
    __shared__ float s_adjT[2][SS][24];   // s_adjT[e][j][i] = sub_adj[i][j]
    __shared__ int   s_rt[2][2];

    const int tid = threadIdx.x;
    const int e = tid >> 7, l = tid & 127;
    const int b0 = blockIdx.x * 2;

    if (tid < 2 * SS) s_sid[tid / SS][tid % SS] = sample_ids[b0 * SS + tid];
    if (tid < 4) s_rt[tid >> 1][tid & 1] = roots[b0 * 2 + tid];
    __syncthreads();

    for (int id = tid; id < 2 * SS * SS; id += 256) {
        int ee = id / 400, rem = id % 400, jj = rem / SS, ii = rem % SS;
        s_adjT[ee][jj][ii] =
            __ldg(&adj[(long)s_sid[ee][ii] * NN + s_sid[ee][jj]]);
    }
    __syncthreads();

    // full prefetch: 20 independent L2 loads in flight
    float2 ax[SS];
#pragma unroll
    for (int j = 0; j < SS; j++)
        ax[j] = __ldg((const float2*)&g_AX1[(long)s_sid[e][j] * 256 + l * 2]);

    const float2 bc = __ldg((const float2*)&b1[l * 2]);

    // H0[p] = (h[2p],h[2p+1]) for column 0; H1 for column 1
    unsigned long long H0[10], H1[10];
    {
        unsigned long long b0p = pk2(bc.x, bc.x);
        unsigned long long b1p = pk2(bc.y, bc.y);
#pragma unroll
        for (int p = 0; p < 10; p++) { H0[p] = b0p; H1[p] = b1p; }
    }

#pragma unroll
    for (int j = 0; j < SS; j++) {
        ulonglong2 A0 = *(const ulonglong2*)&s_adjT[e][j][0];
        ulonglong2 A1 = *(const ulonglong2*)&s_adjT[e][j][4];
        ulonglong2 A2 = *(const ulonglong2*)&s_adjT[e][j][8];
        ulonglong2 A3 = *(const ulonglong2*)&s_adjT[e][j][12];
        ulonglong2 A4 = *(const ulonglong2*)&s_adjT[e][j][16];
        unsigned long long ax0 = pk2(ax[j].x, ax[j].x);
        unsigned long long ax1v = pk2(ax[j].y, ax[j].y);
        H0[0] = fma2_(A0.x, ax0, H0[0]);  H1[0] = fma2_(A0.x, ax1v, H1[0]);
        H0[1] = fma2_(A0.y, ax0, H0[1]);  H1[1] = fma2_(A0.y, ax1v, H1[1]);
        H0[2] = fma2_(A1.x, ax0, H0[2]);  H1[2] = fma2_(A1.x, ax1v, H1[2]);
        H0[3] = fma2_(A1.y, ax0, H0[3]);  H1[3] = fma2_(A1.y, ax1v, H1[3]);
        H0[4] = fma2_(A2.x, ax0, H0[4]);  H1[4] = fma2_(A2.x, ax1v, H1[4]);
        H0[5] = fma2_(A2.y, ax0, H0[5]);  H1[5] = fma2_(A2.y, ax1v, H1[5]);
        H0[6] = fma2_(A3.x, ax0, H0[6]);  H1[6] = fma2_(A3.x, ax1v, H1[6]);
        H0[7] = fma2_(A3.y, ax0, H0[7]);  H1[7] = fma2_(A3.y, ax1v, H1[7]);
        H0[8] = fma2_(A4.x, ax0, H0[8]);  H1[8] = fma2_(A4.x, ax1v, H1[8]);
        H0[9] = fma2_(A4.y, ax0, H0[9]);  H1[9] = fma2_(A4.y, ax1v, H1[9]);
    }

    const int r0 = s_rt[e][0], r1 = s_rt[e][1];
    float2 t0 = make_float2(0.f, 0.f);
    float2 t1 = make_float2(0.f, 0.f);
#pragma unroll
    for (int p = 0; p < 10; p++) {
        float2 ha = upk2(H0[p]);   // col0: rows 2p, 2p+1
        float2 hb = upk2(H1[p]);   // col1: rows 2p, 2p+1
        float h0a = fmaxf(ha.x, 0.f), h0b = fmaxf(ha.y, 0.f);
        float h1a = fmaxf(hb.x, 0.f), h1b = fmaxf(hb.y, 0.f);
        float wa0 = s_adjT[e][2 * p][r0],     wb0 = s_adjT[e][2 * p + 1][r0];
        float wa1 = s_adjT[e][2 * p][r1],     wb1 = s_adjT[e][2 * p + 1][r1];
        t0.x = fmaf(wa0, h0a, t0.x); t0.x = fmaf(wb0, h0b, t0.x);
        t0.y = fmaf(wa0, h1a, t0.y); t0.y = fmaf(wb0, h1b, t0.y);
        t1.x = fmaf(wa1, h0a, t1.x); t1.x = fmaf(wb1, h0b, t1.x);
        t1.y = fmaf(wa1, h1a, t1.y); t1.y = fmaf(wb1, h1b, t1.y);
    }

    const long base = (long)(b0 + e) * 512;
    *(float2*)&g_t2[base + l * 2]       = t0;
    *(float2*)&g_t2[base + 256 + l * 2] = t1;
}

// ---------------------------------------------------------------------------
// Kernel D: tail, 32 elements per block, 256 threads, 96KB dynamic smem.
// Double-buffered weight staging: next chunk's LDGs issue BEFORE computing
// the current chunk; STS after compute; one barrier per chunk.
// dsm (floats): bufA[0:16384) t2(64x256) -> x[0:8192), y1[8192:12288),
//   y2[12288:14336); wb0=[16384:20480), wb1=[20480:24576).
// ---------------------------------------------------------------------------
__global__ __launch_bounds__(256) void tail_kernel(
    const int*   __restrict__ user_idx,
    const int*   __restrict__ item_idx,
    const float* __restrict__ uid_emb,
    const float* __restrict__ sid_emb,
    const float* __restrict__ W2, const float* __restrict__ b2,
    const float* __restrict__ mW0, const float* __restrict__ mb0,
    const float* __restrict__ mW1, const float* __restrict__ mb1,
    const float* __restrict__ mW2, const float* __restrict__ mb2,
    float* __restrict__ out)
{
    extern __shared__ float dsm[];
    float* bufA = dsm;            // 16384 floats
    float* wb0  = dsm + 16384;    // 4096 floats
    float* wb1  = dsm + 20480;    // 4096 floats

    const int tid = threadIdx.x;
    const int tx = tid & 31, ty = tid >> 5;
    const int b0 = blockIdx.x * 32;
    const int sk = tid >> 5;          // staging row-group (= ty)
    const int sq4 = tid & 31;         // staging quad col

    // load t2 for 32 elements (16384 floats, contiguous)
    {
        const float4* src = (const float4*)(g_t2 + (long)b0 * 512);
        for (int id = tid; id < 4096; id += 256) ((float4*)bufA)[id] = src[id];
    }

    // stage W2 chunk 0 into wb0 (rows 0..31 x 128)
#pragma unroll
    for (int p = 0; p < 4; p++) {
        int k = p * 8 + sk;
        *(float4*)&wb0[k * 128 + sq4 * 4] =
            *(const float4*)&W2[(long)k * 128 + sq4 * 4];
    }
    __syncthreads();

    // ---- ft = t2 @ W2: 64 rows (er = ty+8s, s<8) x 128 cols, K=256 ----
    unsigned long long f2[8][2];
#pragma unroll
    for (int s = 0; s < 8; s++) { f2[s][0] = 0ULL; f2[s][1] = 0ULL; }

#pragma unroll
    for (int ch = 0; ch < 8; ch++) {
        float* wcur = (ch & 1) ? wb1 : wb0;
        float* wnxt = (ch & 1) ? wb0 : wb1;
        const int c0 = ch * 32;
        float4 pre[4];
        if (ch < 7) {
#pragma unroll
            for (int p = 0; p < 4; p++) {
                int k = p * 8 + sk;
                pre[p] = *(const float4*)&W2[(long)(c0 + 32 + k) * 128 + sq4 * 4];
            }
        }
#pragma unroll
        for (int kk4 = 0; kk4 < 8; kk4++) {
            float4 tv[8];
#pragma unroll
            for (int s = 0; s < 8; s++)
                tv[s] = *(const float4*)&bufA[(ty + 8 * s) * 256 + c0 + kk4 * 4];
#pragma unroll
            for (int u = 0; u < 4; u++) {
                ulonglong2 wp = *(const ulonglong2*)&wcur[(kk4 * 4 + u) * 128 + tx * 4];
#pragma unroll
                for (int s = 0; s < 8; s++) {
                    float t = ((const float*)&tv[s])[u];
                    unsigned long long tb = pk2(t, t);
                    f2[s][0] = fma2_(tb, wp.x, f2[s][0]);
                    f2[s][1] = fma2_(tb, wp.y, f2[s][1]);
                }
            }
        }
        if (ch < 7) {
#pragma unroll
            for (int p = 0; p < 4; p++) {
                int k = p * 8 + sk;
                *(float4*)&wnxt[k * 128 + sq4 * 4] = pre[p];
            }
        }
        __syncthreads();
    }

    // unpack + merge with id_vec: x[e][r*128+d] = 0.6*emb + 0.4*relu(f + b2)
    float f[8][4];
#pragma unroll
    for (int s = 0; s < 8; s++) {
        float2 p0 = upk2(f2[s][0]);
        float2 p1 = upk2(f2[s][1]);
        f[s][0] = p0.x; f[s][1] = p0.y; f[s][2] = p1.x; f[s][3] = p1.y;
    }
    {
        float4 bv = *(const float4*)&b2[tx * 4];
#pragma unroll
        for (int s = 0; s < 8; s++) {
            int er = ty + 8 * s;
            int e = er >> 1, r = er & 1;
            const float* emb = (r == 0)
                ? &uid_emb[(long)__ldg(&user_idx[b0 + e]) * DD]
                : &sid_emb[(long)__ldg(&item_idx[b0 + e]) * DD];
            float4 idv = __ldg((const float4*)&emb[tx * 4]);
            f[s][0] = 0.6f * idv.x + 0.4f * fmaxf(f[s][0] + bv.x, 0.f);
            f[s][1] = 0.6f * idv.y + 0.4f * fmaxf(f[s][1] + bv.y, 0.f);
            f[s][2] = 0.6f * idv.z + 0.4f * fmaxf(f[s][2] + bv.z, 0.f);
            f[s][3] = 0.6f * idv.w + 0.4f * fmaxf(f[s][3] + bv.w, 0.f);
        }
    }
    __syncthreads();   // all t2 reads done; safe to overwrite bufA[0:8192)
#pragma unroll
    for (int s = 0; s < 8; s++) {
        int er = ty + 8 * s;
        int e = er >> 1, r = er & 1;
        *(float4*)&bufA[e * 256 + r * 128 + tx * 4] = *(float4*)&f[s][0];
    }
    // stage mW0 chunk 0 into wb0
#pragma unroll
    for (int p = 0; p < 4; p++) {
        int k = p * 8 + sk;
        *(float4*)&wb0[k * 128 + sq4 * 4] =
            *(const float4*)&mW0[(long)k * 128 + sq4 * 4];
    }
    __syncthreads();

    // ---- MLP0: y1 = relu(x @ mW0 + mb0): elems e = ty+8s (s<4), cols tx*4 ----
    unsigned long long g2[4][2];
#pragma unroll
    for (int s = 0; s < 4; s++) { g2[s][0] = 0ULL; g2[s][1] = 0ULL; }

#pragma unroll
    for (int ch = 0; ch < 8; ch++) {
        float* wcur = (ch & 1) ? wb1 : wb0;
        float* wnxt = (ch & 1) ? wb0 : wb1;
        const int c0 = ch * 32;
        float4 pre[4];
        if (ch < 7) {
#pragma unroll
            for (int p = 0; p < 4; p++) {
                int k = p * 8 + sk;
                pre[p] = *(const float4*)&mW0[(long)(c0 + 32 + k) * 128 + sq4 * 4];
            }
        }
#pragma unroll
        for (int kk4 = 0; kk4 < 8; kk4++) {
            float4 xv[4];
#pragma unroll
            for (int s = 0; s < 4; s++)
                xv[s] = *(const float4*)&bufA[(ty + 8 * s) * 256 + c0 + kk4 * 4];
#pragma unroll
            for (int u = 0; u < 4; u++) {
                ulonglong2 wp = *(const ulonglong2*)&wcur[(kk4 * 4 + u) * 128 + tx * 4];
#pragma unroll
                for (int s = 0; s < 4; s++) {
                    float x = ((const float*)&xv[s])[u];
                    unsigned long long xb = pk2(x, x);
                    g2[s][0] = fma2_(xb, wp.x, g2[s][0]);
                    g2[s][1] = fma2_(xb, wp.y, g2[s][1]);
                }
            }
        }
        if (ch < 7) {
#pragma unroll
            for (int p = 0; p < 4; p++) {
                int k = p * 8 + sk;
                *(float4*)&wnxt[k * 128 + sq4 * 4] = pre[p];
            }
        }
        __syncthreads();
    }
    {
        float4 bv = __ldg((const float4*)&mb0[tx * 4]);
#pragma unroll
        for (int s = 0; s < 4; s++) {
            int e = ty + 8 * s;
            float2 p0 = upk2(g2[s][0]);
            float2 p1 = upk2(g2[s][1]);
            float4 y;
            y.x = fmaxf(p0.x + bv.x, 0.f); y.y = fmaxf(p0.y + bv.y, 0.f);
            y.z = fmaxf(p1.x + bv.z, 0.f); y.w = fmaxf(p1.y + bv.w, 0.f);
            *(float4*)&bufA[8192 + e * 128 + tx * 4] = y;   // y1[e][128]
        }
    }
    // stage mW1 chunk 0 (rows 0..63 x 64 = 4096 floats) into wb0
#pragma unroll
    for (int p = 0; p < 4; p++) {
        int id = p * 256 + tid;
        int k = id >> 4, dq = id & 15;
        *(float4*)&wb0[k * 64 + dq * 4] =
            *(const float4*)&mW1[(long)k * 64 + dq * 4];
    }
    __syncthreads();

    // ---- MLP1: y2 = relu(y1 @ mW1 + mb1): elems e = ty+8s (s<4), cols tx*2 ----
    {
        const int oo = tx * 2;
        unsigned long long a2[4];
#pragma unroll
        for (int s = 0; s < 4; s++) a2[s] = 0ULL;
#pragma unroll
        for (int ch = 0; ch < 2; ch++) {
            float* wcur = ch ? wb1 : wb0;
            const int c0 = ch * 64;
            float4 pre[4];
            if (ch == 0) {
#pragma unroll
                for (int p = 0; p < 4; p++) {
                    int id = p * 256 + tid;
                    int k = id >> 4, dq = id & 15;
                    pre[p] = *(const float4*)&mW1[(long)(64 + k) * 64 + dq * 4];
                }
            }
#pragma unroll
            for (int kk4 = 0; kk4 < 16; kk4++) {
                float4 yv[4];
#pragma unroll
                for (int s = 0; s < 4; s++)
                    yv[s] = *(const float4*)&bufA[8192 + (ty + 8 * s) * 128 + c0 + kk4 * 4];
#pragma unroll
                for (int u = 0; u < 4; u++) {
                    unsigned long long wp =
                        *(const unsigned long long*)&wcur[(kk4 * 4 + u) * 64 + oo];
#pragma unroll
                    for (int s = 0; s < 4; s++) {
                        float y = ((const float*)&yv[s])[u];
                        a2[s] = fma2_(pk2(y, y), wp, a2[s]);
                    }
                }
            }
            if (ch == 0) {
#pragma unroll
                for (int p = 0; p < 4; p++) {
                    int id = p * 256 + tid;
                    int k = id >> 4, dq = id & 15;
                    *(float4*)&wb1[k * 64 + dq * 4] = pre[p];
                }
            }
            __syncthreads();
        }
        float2 bv = __ldg((const float2*)&mb1[oo]);
#pragma unroll
        for (int s = 0; s < 4; s++) {
            int e = ty + 8 * s;
            float2 av = upk2(a2[s]);
            bufA[12288 + e * 64 + oo]     = fmaxf(av.x + bv.x, 0.f);
            bufA[12288 + e * 64 + oo + 1] = fmaxf(av.y + bv.y, 0.f);
        }
    }
    __syncthreads();

    // ---- MLP2: warp ty handles elements ty+8s (s<4) ----
    {
        float wlo = __ldg(&mW2[tx]);
        float whi = __ldg(&mW2[32 + tx]);
        float bias = __ldg(&mb2[0]);
#pragma unroll
        for (int s = 0; s < 4; s++) {
            int e = ty + 8 * s;
            float p = bufA[12288 + e * 64 + tx] * wlo +
                      bufA[12288 + e * 64 + 32 + tx] * whi;
#pragma unroll
            for (int o = 16; o > 0; o >>= 1)
                p += __shfl_xor_sync(0xffffffffu, p, o);
            if (tx == 0) out[b0 + e] = fmaxf(p + bias, 0.f);
        }
    }
}

// ---------------------------------------------------------------------------
extern "C" void kernel_launch(void* const* d_in, const int* in_sizes, int n_in,
                              void* d_out, int out_size)
{
    const int*   user_indexes = (const int*)  d_in[0];
    const int*   item_indexes = (const int*)  d_in[1];
    const int*   sample_ids   = (const int*)  d_in[2];
    const int*   roots        = (const int*)  d_in[3];
    const float* user_infos   = (const float*)d_in[4];
    const float* item_infos   = (const float*)d_in[5];
    const float* adj_matrix   = (const float*)d_in[6];
    const float* uid_emb      = (const float*)d_in[7];
    const float* sid_emb      = (const float*)d_in[8];
    const float* Wu           = (const float*)d_in[9];
    const float* bu           = (const float*)d_in[10];
    const float* Wi           = (const float*)d_in[11];
    const float* bi           = (const float*)d_in[12];
    const float* W1           = (const float*)d_in[13];
    const float* b1           = (const float*)d_in[14];
    const float* W2           = (const float*)d_in[15];
    const float* b2           = (const float*)d_in[16];
    const float* mW0          = (const float*)d_in[17];
    const float* mb0          = (const float*)d_in[18];
    const float* mW1          = (const float*)d_in[19];
    const float* mb1          = (const float*)d_in[20];
    const float* mW2          = (const float*)d_in[21];
    const float* mb2          = (const float*)d_in[22];
    float* out = (float*)d_out;

    const int TAIL_SMEM = 24576 * sizeof(float);   // 96 KB
    cudaFuncSetAttribute(tail_kernel,
                         cudaFuncAttributeMaxDynamicSharedMemorySize, TAIL_SMEM);

    adjx_kernel<<<NN, DD>>>(user_infos, item_infos, Wu, bu, Wi, bi);
    ax1_kernel<<<(NN + 15) / 16, 256>>>(W1);
    mix_kernel<<<BB / 2, 256>>>(sample_ids, roots, adj_matrix, b1);
    tail_kernel<<<BB / 32, 256, TAIL_SMEM>>>(user_indexes, item_indexes,
                                             uid_emb, sid_emb,
                                             W2, b2, mW0, mb0, mW1, mb1,
                                             mW2, mb2, out);
}